// round 13
// baseline (speedup 1.0000x reference)
#include <cuda_runtime.h>
#include <cuda_bf16.h>
#include <cuda_fp16.h>
#include <stdint.h>
#include <math.h>

#define B_  2
#define L_  2048
#define D_  512
#define H_  8
#define KS_ 8

// ======================= scratch (device globals) ==========================
__device__ __nv_bfloat16 g_q_hi [(size_t)B_*L_*D_];
__device__ __nv_bfloat16 g_q_lo [(size_t)B_*L_*D_];
__device__ __nv_bfloat16 g_k_hi [(size_t)B_*L_*D_];
__device__ __nv_bfloat16 g_k_lo [(size_t)B_*L_*D_];
__device__ __nv_bfloat16 g_v_hi [(size_t)B_*L_*D_];
__device__ __nv_bfloat16 g_v_lo [(size_t)B_*L_*D_];
// concatenated: A4 = [WkT | Wo'], B4 = [WqT | WvT], C4 = [MT | P]
__device__ __nv_bfloat16 g_A4_hi[(size_t)2*H_*D_*D_];
__device__ __nv_bfloat16 g_A4_lo[(size_t)2*H_*D_*D_];
__device__ __nv_bfloat16 g_B4_hi[(size_t)2*H_*D_*D_];
__device__ __nv_bfloat16 g_B4_lo[(size_t)2*H_*D_*D_];
__device__ __nv_bfloat16 g_C4_hi[(size_t)2*H_*D_*D_];
__device__ __nv_bfloat16 g_C4_lo[(size_t)2*H_*D_*D_];
__device__ __nv_bfloat16 g_t_hi [(size_t)B_*H_*L_*D_];
__device__ __nv_bfloat16 g_t_lo [(size_t)B_*H_*L_*D_];
__device__ __half        g_Z_hi [(size_t)B_*H_*L_*D_];   // Z[b,h,m,e]
__device__ __half        g_Z_lo [(size_t)B_*H_*L_*D_];
__device__ __half        g_ZT_hi[(size_t)B_*D_*H_*L_];   // ZT[b,e,h*L+m]
__device__ __half        g_ZT_lo[(size_t)B_*D_*H_*L_];
__device__ __half        g_at_h [(size_t)B_*L_*H_*L_];   // fp16 single-limb attn
__device__ float         g_part [(size_t)B_*KS_*L_*D_];

// ======================= small helpers ======================================
__device__ __forceinline__ uint32_t smem_u32(const void* p) {
    uint32_t a;
    asm("{ .reg .u64 t; cvta.to.shared.u64 t, %1; cvt.u32.u64 %0, t; }"
        : "=r"(a) : "l"(p));
    return a;
}
__device__ __forceinline__ uint32_t swz128(uint32_t o) { return o ^ ((o >> 3) & 0x70); }

__device__ __forceinline__ void cp16(uint32_t s, const void* g) {
    asm volatile("cp.async.cg.shared.global [%0], [%1], 16;" :: "r"(s), "l"(g));
}
#define CP_COMMIT() asm volatile("cp.async.commit_group;" ::: "memory")

__device__ __forceinline__ void ldm4(uint32_t* r, uint32_t a) {
    asm volatile("ldmatrix.sync.aligned.m8n8.x4.shared.b16 {%0,%1,%2,%3}, [%4];"
                 : "=r"(r[0]), "=r"(r[1]), "=r"(r[2]), "=r"(r[3]) : "r"(a));
}
__device__ __forceinline__ void mma_bf16(float* c, const uint32_t* a, const uint32_t* b) {
    asm volatile("mma.sync.aligned.m16n8k16.row.col.f32.bf16.bf16.f32 "
                 "{%0,%1,%2,%3}, {%4,%5,%6,%7}, {%8,%9}, {%0,%1,%2,%3};"
                 : "+f"(c[0]), "+f"(c[1]), "+f"(c[2]), "+f"(c[3])
                 : "r"(a[0]), "r"(a[1]), "r"(a[2]), "r"(a[3]), "r"(b[0]), "r"(b[1]));
}
__device__ __forceinline__ void mma_f16(float* c, const uint32_t* a, const uint32_t* b) {
    asm volatile("mma.sync.aligned.m16n8k16.row.col.f32.f16.f16.f32 "
                 "{%0,%1,%2,%3}, {%4,%5,%6,%7}, {%8,%9}, {%0,%1,%2,%3};"
                 : "+f"(c[0]), "+f"(c[1]), "+f"(c[2]), "+f"(c[3])
                 : "r"(a[0]), "r"(a[1]), "r"(a[2]), "r"(a[3]), "r"(b[0]), "r"(b[1]));
}
__device__ __forceinline__ void split2(float x, __nv_bfloat16& h, __nv_bfloat16& l) {
    h = __float2bfloat16(x);
    l = __float2bfloat16(x - __bfloat162float(h));
}
__device__ __forceinline__ void split_pack(float2 v, uint32_t& hi, uint32_t& lo) {
    __nv_bfloat16 h0, l0, h1, l1;
    split2(v.x, h0, l0);
    split2(v.y, h1, l1);
    hi = ((uint32_t)__bfloat16_as_ushort(h1) << 16) | __bfloat16_as_ushort(h0);
    lo = ((uint32_t)__bfloat16_as_ushort(l1) << 16) | __bfloat16_as_ushort(l0);
}
__device__ __forceinline__ void split_pack_h(float2 v, uint32_t& hi, uint32_t& lo) {
    __half h0 = __float2half(v.x);
    __half l0 = __float2half(v.x - __half2float(h0));
    __half h1 = __float2half(v.y);
    __half l1 = __float2half(v.y - __half2float(h1));
    hi = ((uint32_t)__half_as_ushort(h1) << 16) | __half_as_ushort(h0);
    lo = ((uint32_t)__half_as_ushort(l1) << 16) | __half_as_ushort(l0);
}

// ============ persistent multi-limb HMMA GEMM (KC=64, 3-stage) ==============
// OUT: 0 fp32, 1 bf16 hi/lo pair, 2 f16 hi/lo pair
// AL:  2 = A two bf16 limbs (3 MMAs bf16), 1 = A one f16 limb (2 MMAs f16)
#define KC       64
#define TILE_B   (128 * 128)

struct TileP {
    const __nv_bfloat16 *ah, *al, *bh, *bl;
    long coff;
};

template <int OUT, int AL>
__global__ __launch_bounds__(256, 1)
void mma_gemm(const __nv_bfloat16* __restrict__ Ahi, const __nv_bfloat16* __restrict__ Alo,
              const __nv_bfloat16* __restrict__ Bhi, const __nv_bfloat16* __restrict__ Blo,
              float* __restrict__ C, __nv_bfloat16* __restrict__ Chi,
              __nv_bfloat16* __restrict__ Clo,
              int ntiles, int gx, int gy,
              int K, int lda, int ldb, int ldc,
              long sA, long sB, int adiv, int amod, int bdiv, int bmod,
              int azmod, long sA2, long sB2,
              int czdiv, long sC1, int czmod, long sC2, float alpha)
{
    constexpr int ATB = AL * TILE_B;
    constexpr int STB = (AL + 2) * TILE_B;

    extern __shared__ char smem[];
    const uint32_t sb = smem_u32(smem);
    const int tid  = threadIdx.x;
    const int lane = tid & 31, wid = tid >> 5;
    const int moff = (wid & 1) * 64;
    const int noff = (wid >> 1) * 32;

    int t0 = blockIdx.x;
    if (t0 >= ntiles) return;

    auto tileinfo = [&](int t) -> TileP {
        const int gxy = gx * gy;
        const int z = t / gxy;
        const int r = t - z * gxy;
        const int ty = r / gx;
        const int tx = r - ty * gx;
        const long aoff = (long)((z / adiv) % amod) * sA + (long)(z % azmod) * sA2
                          + (long)ty * 128 * lda;
        const long boff = (long)((z / bdiv) % bmod) * sB + (long)(z % azmod) * sB2
                          + (long)tx * 128 * ldb;
        TileP p;
        p.ah = Ahi + aoff;  p.al = Alo + aoff;
        p.bh = Bhi + boff;  p.bl = Blo + boff;
        p.coff = (long)(z / czdiv) * sC1 + (long)(z % czmod) * sC2
                 + (long)ty * 128 * ldc + (long)tx * 128;
        return p;
    };

#define LOADT(T, cidx, stg) do {                                                 \
        const uint32_t st = sb + (stg) * STB;                                    \
        const int k0 = (cidx) * KC;                                              \
        _Pragma("unroll")                                                        \
        for (int it = 0; it < 4; it++) {                                         \
            const int idx = tid + it * 256;                                      \
            const int row = idx >> 3, ch = idx & 7;                              \
            const uint32_t so = swz128(row * 128 + ch * 16);                     \
            const long goA = (long)row * lda + k0 + ch * 8;                      \
            const long goB = (long)row * ldb + k0 + ch * 8;                      \
            cp16(st + so, (T).ah + goA);                                         \
            if (AL == 2) cp16(st + TILE_B + so, (T).al + goA);                   \
            cp16(st + ATB + so,          (T).bh + goB);                          \
            cp16(st + ATB + TILE_B + so, (T).bl + goB);                          \
        }                                                                        \
    } while (0)

    const int NC = K / KC;
    const int stride = gridDim.x;

    TileP cur = tileinfo(t0);
    LOADT(cur, 0, 0); CP_COMMIT();
    LOADT(cur, 1, 1); CP_COMMIT();
    int lstage = 2;
    int cstage = 0;

    const int arow = (lane & 7) + ((lane >> 3) & 1) * 8;
    const int ach  = (lane >> 4);
    const int brow = (lane & 7) + ((lane >> 4) & 1) * 8;
    const int bch  = ((lane >> 3) & 1);
    const int gq = lane >> 2, tg = lane & 3;

    for (int t = t0; t < ntiles; t += stride) {
        const int tn = t + stride;
        const bool has_next = tn < ntiles;
        TileP nxt = has_next ? tileinfo(tn) : cur;

        float acc[4][4][4];
#pragma unroll
        for (int a = 0; a < 4; a++)
#pragma unroll
            for (int b = 0; b < 4; b++)
#pragma unroll
                for (int c = 0; c < 4; c++) acc[a][b][c] = 0.f;

        for (int c = 0; c < NC; c++) {
            asm volatile("cp.async.wait_group 1;" ::: "memory");
            __syncthreads();
            const int cc = c + 2;
            if (cc < NC) {
                LOADT(cur, cc, lstage);
            } else if (has_next && cc - NC < 2) {
                LOADT(nxt, cc - NC, lstage);
            }
            CP_COMMIT();
            lstage = (lstage == 2) ? 0 : lstage + 1;

            const uint32_t st = sb + cstage * STB;
            cstage = (cstage == 2) ? 0 : cstage + 1;
#pragma unroll
            for (int kk = 0; kk < 4; kk++) {
                uint32_t ah[4][4], al[4][4], bh[4][2], bl[4][2];
#pragma unroll
                for (int mf = 0; mf < 4; mf++) {
                    uint32_t ad = st + swz128((moff + mf * 16 + arow) * 128 + (kk * 2 + ach) * 16);
                    ldm4(ah[mf], ad);
                    if (AL == 2) ldm4(al[mf], ad + TILE_B);
                }
#pragma unroll
                for (int p = 0; p < 2; p++) {
                    uint32_t bd = st + ATB +
                                  swz128((noff + p * 16 + brow) * 128 + (kk * 2 + bch) * 16);
                    uint32_t r[4];
                    ldm4(r, bd);
                    bh[2 * p][0] = r[0]; bh[2 * p][1] = r[1];
                    bh[2 * p + 1][0] = r[2]; bh[2 * p + 1][1] = r[3];
                    ldm4(r, bd + TILE_B);
                    bl[2 * p][0] = r[0]; bl[2 * p][1] = r[1];
                    bl[2 * p + 1][0] = r[2]; bl[2 * p + 1][1] = r[3];
                }
#pragma unroll
                for (int mf = 0; mf < 4; mf++)
#pragma unroll
                    for (int nf = 0; nf < 4; nf++) {
                        if (AL == 2) {
                            mma_bf16(acc[mf][nf], ah[mf], bh[nf]);
                            mma_bf16(acc[mf][nf], ah[mf], bl[nf]);
                            mma_bf16(acc[mf][nf], al[mf], bh[nf]);
                        } else {
                            mma_f16(acc[mf][nf], ah[mf], bh[nf]);
                            mma_f16(acc[mf][nf], ah[mf], bl[nf]);
                        }
                    }
            }
        }

        // ---- epilogue ----
#pragma unroll
        for (int mf = 0; mf < 4; mf++)
#pragma unroll
            for (int nf = 0; nf < 4; nf++) {
                const long row = moff + mf * 16 + gq;
                const long col = noff + nf * 8 + tg * 2;
                float v0 = alpha * acc[mf][nf][0];
                float v1 = alpha * acc[mf][nf][1];
                float v2 = alpha * acc[mf][nf][2];
                float v3 = alpha * acc[mf][nf][3];
                if (OUT == 0) {
                    float2 p0 = {v0, v1}, p1 = {v2, v3};
                    *reinterpret_cast<float2*>(C + cur.coff + row * ldc + col)       = p0;
                    *reinterpret_cast<float2*>(C + cur.coff + (row + 8) * ldc + col) = p1;
                } else {
                    uint32_t hp0, lp0, hp1, lp1;
                    if (OUT == 1) {
                        split_pack({v0, v1}, hp0, lp0);
                        split_pack({v2, v3}, hp1, lp1);
                    } else {
                        split_pack_h({v0, v1}, hp0, lp0);
                        split_pack_h({v2, v3}, hp1, lp1);
                    }
                    *reinterpret_cast<uint32_t*>(Chi + cur.coff + row * ldc + col)       = hp0;
                    *reinterpret_cast<uint32_t*>(Clo + cur.coff + row * ldc + col)       = lp0;
                    *reinterpret_cast<uint32_t*>(Chi + cur.coff + (row + 8) * ldc + col) = hp1;
                    *reinterpret_cast<uint32_t*>(Clo + cur.coff + (row + 8) * ldc + col) = lp1;
                }
            }
        cur = nxt;
    }
#undef LOADT
}

#define SMEM_T2 (3 * 4 * TILE_B)   // AL=2: 192 KB
#define SMEM_T1 (3 * 3 * TILE_B)   // AL=1: 144 KB

// ======================= helper kernels =====================================
__global__ __launch_bounds__(256)
void split_qkv(const float4* __restrict__ q, const float4* __restrict__ k,
               const float4* __restrict__ v,
               uint2* __restrict__ qh, uint2* __restrict__ ql,
               uint2* __restrict__ kh, uint2* __restrict__ kl,
               uint2* __restrict__ vh, uint2* __restrict__ vl, int n4)
{
    int i = blockIdx.x * 256 + threadIdx.x;
    if (i >= n4) return;
    const int sel = blockIdx.y;
    const float4* s = (sel == 0) ? q : (sel == 1) ? k : v;
    uint2* hi = (sel == 0) ? qh : (sel == 1) ? kh : vh;
    uint2* lo = (sel == 0) ? ql : (sel == 1) ? kl : vl;
    float4 x = s[i];
    __nv_bfloat16 h[4], l[4];
    split2(x.x, h[0], l[0]);
    split2(x.y, h[1], l[1]);
    split2(x.z, h[2], l[2]);
    split2(x.w, h[3], l[3]);
    hi[i] = *reinterpret_cast<uint2*>(h);
    lo[i] = *reinterpret_cast<uint2*>(l);
}

// merged weight prep: zz = w*8 + h; w<3 transpose-split, w==3 Wo permute-split
__global__ __launch_bounds__(256)
void prep_weights(const float* __restrict__ Wq, const float* __restrict__ Wk,
                  const float* __restrict__ Wv, const float* __restrict__ Wo,
                  __nv_bfloat16* __restrict__ A4hi, __nv_bfloat16* __restrict__ A4lo,
                  __nv_bfloat16* __restrict__ B4hi, __nv_bfloat16* __restrict__ B4lo)
{
    __shared__ float t[32][33];
    const int zz = blockIdx.z;
    const int w = zz >> 3, z = zz & 7;
    const long HDD = (long)H_ * D_ * D_;
    const int tx = threadIdx.x & 31, ty = threadIdx.x >> 5;

    if (w == 3) {
        const int e0 = blockIdx.y * 32, f0 = blockIdx.x * 32;
        const long base = HDD + (long)z * D_ * D_;
#pragma unroll
        for (int r = 0; r < 32; r += 8) {
            const int e = e0 + ty + r, f = f0 + tx;
            float x = Wo[(long)e * (H_ * D_) + (f >> 6) * 512 + z * 64 + (f & 63)];
            __nv_bfloat16 h, l;
            split2(x, h, l);
            long o = base + (long)e * D_ + f;
            A4hi[o] = h; A4lo[o] = l;
        }
        return;
    }

    const float* src = (w == 0) ? Wq : (w == 1) ? Wk : Wv;
    __nv_bfloat16* hi = (w == 0) ? B4hi : (w == 1) ? A4hi : (B4hi + HDD);
    __nv_bfloat16* lo = (w == 0) ? B4lo : (w == 1) ? A4lo : (B4lo + HDD);

    const int e0 = blockIdx.y * 32, d0 = blockIdx.x * 32;
    const float* s = src + (long)z * D_ * D_;
#pragma unroll
    for (int r = 0; r < 32; r += 8)
        t[ty + r][tx] = s[(long)(e0 + ty + r) * D_ + d0 + tx];
    __syncthreads();
    const long base = (long)z * D_ * D_;
#pragma unroll
    for (int r = 0; r < 32; r += 8) {
        float x = t[tx][ty + r];
        __nv_bfloat16 h, l;
        split2(x, h, l);
        long o = base + (long)(d0 + ty + r) * D_ + e0 + tx;
        hi[o] = h; lo[o] = l;
    }
}

// transpose Z[b,h,m,e] -> ZT[b,e,h*L+m], both f16 hi/lo limbs
__global__ __launch_bounds__(256)
void transpose_z(const __half* __restrict__ Zh, const __half* __restrict__ Zl,
                 __half* __restrict__ Th, __half* __restrict__ Tl)
{
    __shared__ __half t0[32][33], t1[32][33];
    const int z = blockIdx.z;              // b*8 + h
    const int b = z >> 3, h = z & 7;
    const int e0 = blockIdx.x * 32, m0 = blockIdx.y * 32;
    const int tx = threadIdx.x & 31, ty = threadIdx.x >> 5;
    const __half* s0 = Zh + ((long)z * L_ + m0) * D_;
    const __half* s1 = Zl + ((long)z * L_ + m0) * D_;
#pragma unroll
    for (int r = 0; r < 32; r += 8) {
        t0[ty + r][tx] = s0[(long)(ty + r) * D_ + e0 + tx];
        t1[ty + r][tx] = s1[(long)(ty + r) * D_ + e0 + tx];
    }
    __syncthreads();
    const long ob = (long)b * D_ * (H_ * L_) + (long)h * L_ + m0;
#pragma unroll
    for (int r = 0; r < 32; r += 8) {
        long o = ob + (long)(e0 + ty + r) * (H_ * L_) + tx;
        Th[o] = t0[tx][ty + r];
        Tl[o] = t1[tx][ty + r];
    }
}

// softmax: in place fp32 [b,h,l,m] + fp16 single-limb copy in [b,l,h,m]
__global__ __launch_bounds__(256)
void softmax_split(float* __restrict__ data, uint2* __restrict__ hi)
{
    const int r = blockIdx.x;
    const int b = r >> 14;
    const int h = (r >> 11) & (H_ - 1);
    const int l = r & (L_ - 1);
    float4* p = reinterpret_cast<float4*>(data + (long)r * L_);
    const long ob4 = ((((long)b * L_ + l) * H_ + h) * L_) >> 2;
    const int tid = threadIdx.x;

    float4 vals[2];
    float vmax = -1e30f;
#pragma unroll
    for (int i = 0; i < 2; i++) {
        vals[i] = p[tid + i * 256];
        vmax = fmaxf(vmax, fmaxf(fmaxf(vals[i].x, vals[i].y), fmaxf(vals[i].z, vals[i].w)));
    }
#pragma unroll
    for (int o = 16; o > 0; o >>= 1) vmax = fmaxf(vmax, __shfl_xor_sync(0xFFFFFFFFu, vmax, o));

    __shared__ float smax[8], ssum[8];
    if ((tid & 31) == 0) smax[tid >> 5] = vmax;
    __syncthreads();
    float m = smax[0];
#pragma unroll
    for (int i = 1; i < 8; i++) m = fmaxf(m, smax[i]);

    float sum = 0.f;
#pragma unroll
    for (int i = 0; i < 2; i++) {
        vals[i].x = __expf(vals[i].x - m);
        vals[i].y = __expf(vals[i].y - m);
        vals[i].z = __expf(vals[i].z - m);
        vals[i].w = __expf(vals[i].w - m);
        sum += (vals[i].x + vals[i].y) + (vals[i].z + vals[i].w);
    }
#pragma unroll
    for (int o = 16; o > 0; o >>= 1) sum += __shfl_xor_sync(0xFFFFFFFFu, sum, o);
    if ((tid & 31) == 0) ssum[tid >> 5] = sum;
    __syncthreads();
    float tot = 0.f;
#pragma unroll
    for (int i = 0; i < 8; i++) tot += ssum[i];
    const float inv = 1.f / tot;
#pragma unroll
    for (int i = 0; i < 2; i++) {
        float4 y;
        y.x = vals[i].x * inv; y.y = vals[i].y * inv;
        y.z = vals[i].z * inv; y.w = vals[i].w * inv;
        p[tid + i * 256] = y;
        __half h0 = __float2half(y.x), h1 = __float2half(y.y);
        __half h2 = __float2half(y.z), h3 = __float2half(y.w);
        uint2 hp;
        hp.x = ((uint32_t)__half_as_ushort(h1) << 16) | __half_as_ushort(h0);
        hp.y = ((uint32_t)__half_as_ushort(h3) << 16) | __half_as_ushort(h2);
        hi[ob4 + tid + i * 256] = hp;
    }
}

// reduce partials: out[b][j] = sum_ks part[b*KS+ks][j]
__global__ __launch_bounds__(256)
void reduce_part(const float4* __restrict__ part, float4* __restrict__ out)
{
    const int LD4 = L_ * D_ / 4;
    long idx = (long)blockIdx.x * 256 + threadIdx.x;
    int b = (int)(idx / LD4);
    long j = idx - (long)b * LD4;
    const float4* p = part + (long)b * KS_ * LD4 + j;
    float4 s = p[0];
#pragma unroll
    for (int ks = 1; ks < KS_; ks++) {
        float4 t = p[(long)ks * LD4];
        s.x += t.x; s.y += t.y; s.z += t.z; s.w += t.w;
    }
    out[idx] = s;
}

// ======================= launch =============================================
extern "C" void kernel_launch(void* const* d_in, const int* in_sizes, int n_in,
                              void* d_out, int out_size)
{
    const float* q  = (const float*)d_in[0];
    const float* k  = (const float*)d_in[1];
    const float* v  = (const float*)d_in[2];
    const float* Wq = (const float*)d_in[3];
    const float* Wk = (const float*)d_in[4];
    const float* Wv = (const float*)d_in[5];
    const float* Wo = (const float*)d_in[6];

    float* out  = (float*)d_out;
    float* attn = out + (long)B_ * L_ * D_;

    static int nsm = 0;
    if (!nsm) {
        cudaDeviceGetAttribute(&nsm, cudaDevAttrMultiProcessorCount, 0);
        cudaFuncSetAttribute(mma_gemm<0, 2>, cudaFuncAttributeMaxDynamicSharedMemorySize, SMEM_T2);
        cudaFuncSetAttribute(mma_gemm<1, 2>, cudaFuncAttributeMaxDynamicSharedMemorySize, SMEM_T2);
        cudaFuncSetAttribute(mma_gemm<2, 2>, cudaFuncAttributeMaxDynamicSharedMemorySize, SMEM_T2);
        cudaFuncSetAttribute(mma_gemm<0, 1>, cudaFuncAttributeMaxDynamicSharedMemorySize, SMEM_T1);
        if (nsm <= 0) nsm = 148;
    }

#define SYM(p, s) cudaGetSymbolAddress((void**)&p, s)
    __nv_bfloat16 *q_hi, *q_lo, *k_hi, *k_lo, *v_hi, *v_lo;
    __nv_bfloat16 *A4_hi, *A4_lo, *B4_hi, *B4_lo, *C4_hi, *C4_lo;
    __nv_bfloat16 *t_hi, *t_lo;
    __half *Z_hi, *Z_lo, *ZT_hi, *ZT_lo, *at_h;
    float *part;
    SYM(q_hi, g_q_hi);  SYM(q_lo, g_q_lo);
    SYM(k_hi, g_k_hi);  SYM(k_lo, g_k_lo);
    SYM(v_hi, g_v_hi);  SYM(v_lo, g_v_lo);
    SYM(A4_hi, g_A4_hi); SYM(A4_lo, g_A4_lo);
    SYM(B4_hi, g_B4_hi); SYM(B4_lo, g_B4_lo);
    SYM(C4_hi, g_C4_hi); SYM(C4_lo, g_C4_lo);
    SYM(t_hi, g_t_hi);   SYM(t_lo, g_t_lo);
    SYM(Z_hi, g_Z_hi);   SYM(Z_lo, g_Z_lo);
    SYM(ZT_hi, g_ZT_hi); SYM(ZT_lo, g_ZT_lo);
    SYM(at_h, g_at_h);
    SYM(part, g_part);
#undef SYM

    const long sLD = (long)L_ * D_;
    const long sLL = (long)L_ * L_;
    const long sDD = (long)D_ * D_;
    const long HDD = (long)H_ * D_ * D_;
    const float inv_sqrt_d = 1.0f / sqrtf((float)D_);

    dim3 blk(256);
    const int n4_in = (B_ * L_ * D_) / 4;

    // launch 0: merged q/k/v splits
    dim3 gsp((n4_in + 255) / 256, 3);
    split_qkv<<<gsp, blk>>>((const float4*)q, (const float4*)k, (const float4*)v,
        (uint2*)q_hi, (uint2*)q_lo, (uint2*)k_hi, (uint2*)k_lo,
        (uint2*)v_hi, (uint2*)v_lo, n4_in);

    // launch 1: merged weight prep
    dim3 gtw(D_ / 32, D_ / 32, 4 * H_);
    prep_weights<<<gtw, blk>>>(Wq, Wk, Wv, Wo, A4_hi, A4_lo, B4_hi, B4_lo);

    // launch 2: C4[z] = A4[z] @ B4[z]^T  (256 tiles)
    mma_gemm<1, 2><<<nsm, blk, SMEM_T2>>>(A4_hi, A4_lo, B4_hi, B4_lo,
        nullptr, C4_hi, C4_lo,
        256, 4, 4, D_, D_, D_, D_, sDD, sDD, 1, 2 * H_, 1, 2 * H_, 1, 0, 0,
        1, sDD, 1, 0, 1.0f);

    // launch 3: Z[b,h,m,e] = v[b] @ P[h]^T  -> f16 pairs, ldc=512 (t-shaped; 1024 tiles)
    mma_gemm<2, 2><<<nsm, blk, SMEM_T2>>>(v_hi, v_lo, C4_hi + HDD, C4_lo + HDD,
        nullptr, (__nv_bfloat16*)Z_hi, (__nv_bfloat16*)Z_lo,
        1024, 4, 16, D_, D_, D_, D_, sLD, sDD, H_, B_, 1, H_, 1, 0, 0,
        H_, (long)H_ * L_ * D_, H_, (long)L_ * D_, 1.0f);

    // launch 4: transpose Z -> ZT[b,e,h*L+m]
    dim3 gtz(D_ / 32, L_ / 32, B_ * H_);
    transpose_z<<<gtz, blk>>>(Z_hi, Z_lo, ZT_hi, ZT_lo);

    // launch 5: t[b,h] = q[b] @ MT[h]^T   (1024 tiles)
    mma_gemm<1, 2><<<nsm, blk, SMEM_T2>>>(q_hi, q_lo, C4_hi, C4_lo,
        nullptr, t_hi, t_lo,
        1024, 4, 16, D_, D_, D_, D_, sLD, sDD, H_, B_, 1, H_, 1, 0, 0,
        1, sLD, 1, 0, 1.0f);

    // launch 6: scores[b,h] = t[b,h] @ k[b]^T / sqrt(D) (4096 tiles)
    mma_gemm<0, 2><<<nsm, blk, SMEM_T2>>>(t_hi, t_lo, k_hi, k_lo,
        attn, nullptr, nullptr,
        4096, 16, 16, D_, D_, D_, L_, sLD, sLD, 1, B_ * H_, H_, B_, 1, 0, 0,
        1, sLL, 1, 0, inv_sqrt_d);

    // launch 7: softmax in place + fp16 single-limb copy in [b,l,h,m] layout
    softmax_split<<<B_ * H_ * L_, blk>>>(attn, (uint2*)at_h);

    // launch 8: out partials, split-K=8 over H*L, A = fp16 attn (1024 tiles)
    mma_gemm<0, 1><<<nsm, blk, SMEM_T1>>>((const __nv_bfloat16*)at_h,
        (const __nv_bfloat16*)at_h,
        (const __nv_bfloat16*)ZT_hi, (const __nv_bfloat16*)ZT_lo,
        part, nullptr, nullptr,
        1024, 4, 16, (H_ * L_) / KS_, H_ * L_, H_ * L_, D_,
        (long)L_ * H_ * L_, (long)D_ * H_ * L_, KS_, B_, KS_, B_,
        KS_, (H_ * L_) / KS_, (H_ * L_) / KS_,
        1, sLD, 1, 0, 1.0f);

    // launch 9: reduce partials -> out
    reduce_part<<<(B_ * L_ * D_ / 4) / 256, blk>>>((const float4*)part, (float4*)out);
}

// round 14
// speedup vs baseline: 1.1324x; 1.1324x over previous
#include <cuda_runtime.h>
#include <cuda_bf16.h>
#include <cuda_fp16.h>
#include <stdint.h>
#include <math.h>

#define B_  2
#define L_  2048
#define D_  512
#define H_  8
#define KS_ 4

// ======================= scratch (device globals) ==========================
__device__ __nv_bfloat16 g_q_hi [(size_t)B_*L_*D_];
__device__ __nv_bfloat16 g_q_lo [(size_t)B_*L_*D_];
__device__ __nv_bfloat16 g_k_hi [(size_t)B_*L_*D_];
__device__ __nv_bfloat16 g_k_lo [(size_t)B_*L_*D_];
__device__ __nv_bfloat16 g_v_hi [(size_t)B_*L_*D_];
__device__ __nv_bfloat16 g_v_lo [(size_t)B_*L_*D_];
// concatenated: A4 = [WkT | Wo'], B4 = [WqT | WvT], C4 = [MT | P]
__device__ __nv_bfloat16 g_A4_hi[(size_t)2*H_*D_*D_];
__device__ __nv_bfloat16 g_A4_lo[(size_t)2*H_*D_*D_];
__device__ __nv_bfloat16 g_B4_hi[(size_t)2*H_*D_*D_];
__device__ __nv_bfloat16 g_B4_lo[(size_t)2*H_*D_*D_];
__device__ __nv_bfloat16 g_C4_hi[(size_t)2*H_*D_*D_];
__device__ __nv_bfloat16 g_C4_lo[(size_t)2*H_*D_*D_];
__device__ __nv_bfloat16 g_t_hi [(size_t)B_*H_*L_*D_];
__device__ __nv_bfloat16 g_t_lo [(size_t)B_*H_*L_*D_];
__device__ __half        g_ZT_h [(size_t)B_*D_*H_*L_];   // fp16 single-limb ZT
__device__ __half        g_at_h [(size_t)B_*L_*H_*L_];   // fp16 single-limb attn
__device__ float         g_part [(size_t)B_*KS_*L_*D_];

// ======================= small helpers ======================================
__device__ __forceinline__ uint32_t smem_u32(const void* p) {
    uint32_t a;
    asm("{ .reg .u64 t; cvta.to.shared.u64 t, %1; cvt.u32.u64 %0, t; }"
        : "=r"(a) : "l"(p));
    return a;
}
__device__ __forceinline__ uint32_t swz128(uint32_t o) { return o ^ ((o >> 3) & 0x70); }

__device__ __forceinline__ void cp16(uint32_t s, const void* g) {
    asm volatile("cp.async.cg.shared.global [%0], [%1], 16;" :: "r"(s), "l"(g));
}
#define CP_COMMIT() asm volatile("cp.async.commit_group;" ::: "memory")

__device__ __forceinline__ void ldm4(uint32_t* r, uint32_t a) {
    asm volatile("ldmatrix.sync.aligned.m8n8.x4.shared.b16 {%0,%1,%2,%3}, [%4];"
                 : "=r"(r[0]), "=r"(r[1]), "=r"(r[2]), "=r"(r[3]) : "r"(a));
}
__device__ __forceinline__ void mma_bf16(float* c, const uint32_t* a, const uint32_t* b) {
    asm volatile("mma.sync.aligned.m16n8k16.row.col.f32.bf16.bf16.f32 "
                 "{%0,%1,%2,%3}, {%4,%5,%6,%7}, {%8,%9}, {%0,%1,%2,%3};"
                 : "+f"(c[0]), "+f"(c[1]), "+f"(c[2]), "+f"(c[3])
                 : "r"(a[0]), "r"(a[1]), "r"(a[2]), "r"(a[3]), "r"(b[0]), "r"(b[1]));
}
__device__ __forceinline__ void mma_f16(float* c, const uint32_t* a, const uint32_t* b) {
    asm volatile("mma.sync.aligned.m16n8k16.row.col.f32.f16.f16.f32 "
                 "{%0,%1,%2,%3}, {%4,%5,%6,%7}, {%8,%9}, {%0,%1,%2,%3};"
                 : "+f"(c[0]), "+f"(c[1]), "+f"(c[2]), "+f"(c[3])
                 : "r"(a[0]), "r"(a[1]), "r"(a[2]), "r"(a[3]), "r"(b[0]), "r"(b[1]));
}
__device__ __forceinline__ void split2(float x, __nv_bfloat16& h, __nv_bfloat16& l) {
    h = __float2bfloat16(x);
    l = __float2bfloat16(x - __bfloat162float(h));
}
__device__ __forceinline__ void split_pack(float2 v, uint32_t& hi, uint32_t& lo) {
    __nv_bfloat16 h0, l0, h1, l1;
    split2(v.x, h0, l0);
    split2(v.y, h1, l1);
    hi = ((uint32_t)__bfloat16_as_ushort(h1) << 16) | __bfloat16_as_ushort(h0);
    lo = ((uint32_t)__bfloat16_as_ushort(l1) << 16) | __bfloat16_as_ushort(l0);
}
__device__ __forceinline__ uint32_t pack_h2(float2 v) {
    __half h0 = __float2half(v.x);
    __half h1 = __float2half(v.y);
    return ((uint32_t)__half_as_ushort(h1) << 16) | __half_as_ushort(h0);
}

// ============ persistent multi-limb HMMA GEMM (KC=64, 3-stage) ==============
// OUT: 0 fp32, 1 bf16 hi/lo pair, 3 fp16 single limb (Chi only)
// AL/BL: limb counts. (2,2)=3 bf16 MMAs; (1,1)=1 f16 MMA.
#define KC       64
#define TILE_B   (128 * 128)

struct TileP {
    const __nv_bfloat16 *ah, *al, *bh, *bl;
    long coff;
};

template <int OUT, int AL, int BL>
__global__ __launch_bounds__(256, 1)
void mma_gemm(const __nv_bfloat16* __restrict__ Ahi, const __nv_bfloat16* __restrict__ Alo,
              const __nv_bfloat16* __restrict__ Bhi, const __nv_bfloat16* __restrict__ Blo,
              float* __restrict__ C, __nv_bfloat16* __restrict__ Chi,
              __nv_bfloat16* __restrict__ Clo,
              int ntiles, int gx, int gy,
              int K, int lda, int ldb, int ldc,
              long sA, long sB, int adiv, int amod, int bdiv, int bmod,
              int azmod, long sA2, long sB2,
              int czdiv, long sC1, int czmod, long sC2, float alpha)
{
    constexpr int ATB = AL * TILE_B;
    constexpr int STB = (AL + BL) * TILE_B;

    extern __shared__ char smem[];
    const uint32_t sb = smem_u32(smem);
    const int tid  = threadIdx.x;
    const int lane = tid & 31, wid = tid >> 5;
    const int moff = (wid & 1) * 64;
    const int noff = (wid >> 1) * 32;

    int t0 = blockIdx.x;
    if (t0 >= ntiles) return;

    auto tileinfo = [&](int t) -> TileP {
        const int gxy = gx * gy;
        const int z = t / gxy;
        const int r = t - z * gxy;
        const int ty = r / gx;
        const int tx = r - ty * gx;
        const long aoff = (long)((z / adiv) % amod) * sA + (long)(z % azmod) * sA2
                          + (long)ty * 128 * lda;
        const long boff = (long)((z / bdiv) % bmod) * sB + (long)(z % azmod) * sB2
                          + (long)tx * 128 * ldb;
        TileP p;
        p.ah = Ahi + aoff;  p.al = Alo + aoff;
        p.bh = Bhi + boff;  p.bl = Blo + boff;
        p.coff = (long)(z / czdiv) * sC1 + (long)(z % czmod) * sC2
                 + (long)ty * 128 * ldc + (long)tx * 128;
        return p;
    };

#define LOADT(T, cidx, stg) do {                                                 \
        const uint32_t st = sb + (stg) * STB;                                    \
        const int k0 = (cidx) * KC;                                              \
        _Pragma("unroll")                                                        \
        for (int it = 0; it < 4; it++) {                                         \
            const int idx = tid + it * 256;                                      \
            const int row = idx >> 3, ch = idx & 7;                              \
            const uint32_t so = swz128(row * 128 + ch * 16);                     \
            const long goA = (long)row * lda + k0 + ch * 8;                      \
            const long goB = (long)row * ldb + k0 + ch * 8;                      \
            cp16(st + so, (T).ah + goA);                                         \
            if (AL == 2) cp16(st + TILE_B + so, (T).al + goA);                   \
            cp16(st + ATB + so, (T).bh + goB);                                   \
            if (BL == 2) cp16(st + ATB + TILE_B + so, (T).bl + goB);             \
        }                                                                        \
    } while (0)

    const int NC = K / KC;
    const int stride = gridDim.x;

    TileP cur = tileinfo(t0);
    LOADT(cur, 0, 0); CP_COMMIT();
    LOADT(cur, 1, 1); CP_COMMIT();
    int lstage = 2;
    int cstage = 0;

    const int arow = (lane & 7) + ((lane >> 3) & 1) * 8;
    const int ach  = (lane >> 4);
    const int brow = (lane & 7) + ((lane >> 4) & 1) * 8;
    const int bch  = ((lane >> 3) & 1);
    const int gq = lane >> 2, tg = lane & 3;

    for (int t = t0; t < ntiles; t += stride) {
        const int tn = t + stride;
        const bool has_next = tn < ntiles;
        TileP nxt = has_next ? tileinfo(tn) : cur;

        float acc[4][4][4];
#pragma unroll
        for (int a = 0; a < 4; a++)
#pragma unroll
            for (int b = 0; b < 4; b++)
#pragma unroll
                for (int c = 0; c < 4; c++) acc[a][b][c] = 0.f;

        for (int c = 0; c < NC; c++) {
            asm volatile("cp.async.wait_group 1;" ::: "memory");
            __syncthreads();
            const int cc = c + 2;
            if (cc < NC) {
                LOADT(cur, cc, lstage);
            } else if (has_next && cc - NC < 2) {
                LOADT(nxt, cc - NC, lstage);
            }
            CP_COMMIT();
            lstage = (lstage == 2) ? 0 : lstage + 1;

            const uint32_t st = sb + cstage * STB;
            cstage = (cstage == 2) ? 0 : cstage + 1;
#pragma unroll
            for (int kk = 0; kk < 4; kk++) {
                uint32_t ah[4][4], al[4][4], bh[4][2], bl[4][2];
#pragma unroll
                for (int mf = 0; mf < 4; mf++) {
                    uint32_t ad = st + swz128((moff + mf * 16 + arow) * 128 + (kk * 2 + ach) * 16);
                    ldm4(ah[mf], ad);
                    if (AL == 2) ldm4(al[mf], ad + TILE_B);
                }
#pragma unroll
                for (int p = 0; p < 2; p++) {
                    uint32_t bd = st + ATB +
                                  swz128((noff + p * 16 + brow) * 128 + (kk * 2 + bch) * 16);
                    uint32_t r[4];
                    ldm4(r, bd);
                    bh[2 * p][0] = r[0]; bh[2 * p][1] = r[1];
                    bh[2 * p + 1][0] = r[2]; bh[2 * p + 1][1] = r[3];
                    if (BL == 2) {
                        ldm4(r, bd + TILE_B);
                        bl[2 * p][0] = r[0]; bl[2 * p][1] = r[1];
                        bl[2 * p + 1][0] = r[2]; bl[2 * p + 1][1] = r[3];
                    }
                }
#pragma unroll
                for (int mf = 0; mf < 4; mf++)
#pragma unroll
                    for (int nf = 0; nf < 4; nf++) {
                        if (AL == 2 && BL == 2) {
                            mma_bf16(acc[mf][nf], ah[mf], bh[nf]);
                            mma_bf16(acc[mf][nf], ah[mf], bl[nf]);
                            mma_bf16(acc[mf][nf], al[mf], bh[nf]);
                        } else {
                            mma_f16(acc[mf][nf], ah[mf], bh[nf]);
                            if (BL == 2) mma_f16(acc[mf][nf], ah[mf], bl[nf]);
                        }
                    }
            }
        }

        // ---- epilogue ----
#pragma unroll
        for (int mf = 0; mf < 4; mf++)
#pragma unroll
            for (int nf = 0; nf < 4; nf++) {
                const long row = moff + mf * 16 + gq;
                const long col = noff + nf * 8 + tg * 2;
                float v0 = alpha * acc[mf][nf][0];
                float v1 = alpha * acc[mf][nf][1];
                float v2 = alpha * acc[mf][nf][2];
                float v3 = alpha * acc[mf][nf][3];
                if (OUT == 0) {
                    float2 p0 = {v0, v1}, p1 = {v2, v3};
                    *reinterpret_cast<float2*>(C + cur.coff + row * ldc + col)       = p0;
                    *reinterpret_cast<float2*>(C + cur.coff + (row + 8) * ldc + col) = p1;
                } else if (OUT == 1) {
                    uint32_t hp0, lp0, hp1, lp1;
                    split_pack({v0, v1}, hp0, lp0);
                    split_pack({v2, v3}, hp1, lp1);
                    *reinterpret_cast<uint32_t*>(Chi + cur.coff + row * ldc + col)       = hp0;
                    *reinterpret_cast<uint32_t*>(Clo + cur.coff + row * ldc + col)       = lp0;
                    *reinterpret_cast<uint32_t*>(Chi + cur.coff + (row + 8) * ldc + col) = hp1;
                    *reinterpret_cast<uint32_t*>(Clo + cur.coff + (row + 8) * ldc + col) = lp1;
                } else {   // OUT == 3: single fp16 limb
                    *reinterpret_cast<uint32_t*>(Chi + cur.coff + row * ldc + col)       = pack_h2({v0, v1});
                    *reinterpret_cast<uint32_t*>(Chi + cur.coff + (row + 8) * ldc + col) = pack_h2({v2, v3});
                }
            }
        cur = nxt;
    }
#undef LOADT
}

#define SMEM_T22 (3 * 4 * TILE_B)   // (2,2): 192 KB
#define SMEM_T11 (3 * 2 * TILE_B)   // (1,1): 96 KB

// ======================= helper kernels =====================================
__global__ __launch_bounds__(256)
void split_qkv(const float4* __restrict__ q, const float4* __restrict__ k,
               const float4* __restrict__ v,
               uint2* __restrict__ qh, uint2* __restrict__ ql,
               uint2* __restrict__ kh, uint2* __restrict__ kl,
               uint2* __restrict__ vh, uint2* __restrict__ vl, int n4)
{
    int i = blockIdx.x * 256 + threadIdx.x;
    if (i >= n4) return;
    const int sel = blockIdx.y;
    const float4* s = (sel == 0) ? q : (sel == 1) ? k : v;
    uint2* hi = (sel == 0) ? qh : (sel == 1) ? kh : vh;
    uint2* lo = (sel == 0) ? ql : (sel == 1) ? kl : vl;
    float4 x = s[i];
    __nv_bfloat16 h[4], l[4];
    split2(x.x, h[0], l[0]);
    split2(x.y, h[1], l[1]);
    split2(x.z, h[2], l[2]);
    split2(x.w, h[3], l[3]);
    hi[i] = *reinterpret_cast<uint2*>(h);
    lo[i] = *reinterpret_cast<uint2*>(l);
}

// merged weight prep: zz = w*8 + h; w<3 transpose-split, w==3 Wo permute-split
__global__ __launch_bounds__(256)
void prep_weights(const float* __restrict__ Wq, const float* __restrict__ Wk,
                  const float* __restrict__ Wv, const float* __restrict__ Wo,
                  __nv_bfloat16* __restrict__ A4hi, __nv_bfloat16* __restrict__ A4lo,
                  __nv_bfloat16* __restrict__ B4hi, __nv_bfloat16* __restrict__ B4lo)
{
    __shared__ float t[32][33];
    const int zz = blockIdx.z;
    const int w = zz >> 3, z = zz & 7;
    const long HDD = (long)H_ * D_ * D_;
    const int tx = threadIdx.x & 31, ty = threadIdx.x >> 5;

    if (w == 3) {
        const int e0 = blockIdx.y * 32, f0 = blockIdx.x * 32;
        const long base = HDD + (long)z * D_ * D_;
#pragma unroll
        for (int r = 0; r < 32; r += 8) {
            const int e = e0 + ty + r, f = f0 + tx;
            float x = Wo[(long)e * (H_ * D_) + (f >> 6) * 512 + z * 64 + (f & 63)];
            __nv_bfloat16 h, l;
            split2(x, h, l);
            long o = base + (long)e * D_ + f;
            A4hi[o] = h; A4lo[o] = l;
        }
        return;
    }

    const float* src = (w == 0) ? Wq : (w == 1) ? Wk : Wv;
    __nv_bfloat16* hi = (w == 0) ? B4hi : (w == 1) ? A4hi : (B4hi + HDD);
    __nv_bfloat16* lo = (w == 0) ? B4lo : (w == 1) ? A4lo : (B4lo + HDD);

    const int e0 = blockIdx.y * 32, d0 = blockIdx.x * 32;
    const float* s = src + (long)z * D_ * D_;
#pragma unroll
    for (int r = 0; r < 32; r += 8)
        t[ty + r][tx] = s[(long)(e0 + ty + r) * D_ + d0 + tx];
    __syncthreads();
    const long base = (long)z * D_ * D_;
#pragma unroll
    for (int r = 0; r < 32; r += 8) {
        float x = t[tx][ty + r];
        __nv_bfloat16 h, l;
        split2(x, h, l);
        long o = base + (long)(d0 + ty + r) * D_ + e0 + tx;
        hi[o] = h; lo[o] = l;
    }
}

// softmax: in place fp32 [b,h,l,m] + fp16 single-limb copy in [b,l,h,m]
__global__ __launch_bounds__(256)
void softmax_split(float* __restrict__ data, uint2* __restrict__ hi)
{
    const int r = blockIdx.x;
    const int b = r >> 14;
    const int h = (r >> 11) & (H_ - 1);
    const int l = r & (L_ - 1);
    float4* p = reinterpret_cast<float4*>(data + (long)r * L_);
    const long ob4 = ((((long)b * L_ + l) * H_ + h) * L_) >> 2;
    const int tid = threadIdx.x;

    float4 vals[2];
    float vmax = -1e30f;
#pragma unroll
    for (int i = 0; i < 2; i++) {
        vals[i] = p[tid + i * 256];
        vmax = fmaxf(vmax, fmaxf(fmaxf(vals[i].x, vals[i].y), fmaxf(vals[i].z, vals[i].w)));
    }
#pragma unroll
    for (int o = 16; o > 0; o >>= 1) vmax = fmaxf(vmax, __shfl_xor_sync(0xFFFFFFFFu, vmax, o));

    __shared__ float smax[8], ssum[8];
    if ((tid & 31) == 0) smax[tid >> 5] = vmax;
    __syncthreads();
    float m = smax[0];
#pragma unroll
    for (int i = 1; i < 8; i++) m = fmaxf(m, smax[i]);

    float sum = 0.f;
#pragma unroll
    for (int i = 0; i < 2; i++) {
        vals[i].x = __expf(vals[i].x - m);
        vals[i].y = __expf(vals[i].y - m);
        vals[i].z = __expf(vals[i].z - m);
        vals[i].w = __expf(vals[i].w - m);
        sum += (vals[i].x + vals[i].y) + (vals[i].z + vals[i].w);
    }
#pragma unroll
    for (int o = 16; o > 0; o >>= 1) sum += __shfl_xor_sync(0xFFFFFFFFu, sum, o);
    if ((tid & 31) == 0) ssum[tid >> 5] = sum;
    __syncthreads();
    float tot = 0.f;
#pragma unroll
    for (int i = 0; i < 8; i++) tot += ssum[i];
    const float inv = 1.f / tot;
#pragma unroll
    for (int i = 0; i < 2; i++) {
        float4 y;
        y.x = vals[i].x * inv; y.y = vals[i].y * inv;
        y.z = vals[i].z * inv; y.w = vals[i].w * inv;
        p[tid + i * 256] = y;
        uint2 hp;
        hp.x = pack_h2({y.x, y.y});
        hp.y = pack_h2({y.z, y.w});
        hi[ob4 + tid + i * 256] = hp;
    }
}

// reduce partials: out[b][j] = sum_ks part[b*KS+ks][j]
__global__ __launch_bounds__(256)
void reduce_part(const float4* __restrict__ part, float4* __restrict__ out)
{
    const int LD4 = L_ * D_ / 4;
    long idx = (long)blockIdx.x * 256 + threadIdx.x;
    int b = (int)(idx / LD4);
    long j = idx - (long)b * LD4;
    const float4* p = part + (long)b * KS_ * LD4 + j;
    float4 s = p[0];
#pragma unroll
    for (int ks = 1; ks < KS_; ks++) {
        float4 t = p[(long)ks * LD4];
        s.x += t.x; s.y += t.y; s.z += t.z; s.w += t.w;
    }
    out[idx] = s;
}

// ======================= launch =============================================
extern "C" void kernel_launch(void* const* d_in, const int* in_sizes, int n_in,
                              void* d_out, int out_size)
{
    const float* q  = (const float*)d_in[0];
    const float* k  = (const float*)d_in[1];
    const float* v  = (const float*)d_in[2];
    const float* Wq = (const float*)d_in[3];
    const float* Wk = (const float*)d_in[4];
    const float* Wv = (const float*)d_in[5];
    const float* Wo = (const float*)d_in[6];

    float* out  = (float*)d_out;
    float* attn = out + (long)B_ * L_ * D_;

    static int nsm = 0;
    if (!nsm) {
        cudaDeviceGetAttribute(&nsm, cudaDevAttrMultiProcessorCount, 0);
        cudaFuncSetAttribute((const void*)mma_gemm<0, 2, 2>, cudaFuncAttributeMaxDynamicSharedMemorySize, SMEM_T22);
        cudaFuncSetAttribute((const void*)mma_gemm<1, 2, 2>, cudaFuncAttributeMaxDynamicSharedMemorySize, SMEM_T22);
        cudaFuncSetAttribute((const void*)mma_gemm<3, 2, 2>, cudaFuncAttributeMaxDynamicSharedMemorySize, SMEM_T22);
        cudaFuncSetAttribute((const void*)mma_gemm<0, 1, 1>, cudaFuncAttributeMaxDynamicSharedMemorySize, SMEM_T11);
        if (nsm <= 0) nsm = 148;
    }

#define SYM(p, s) cudaGetSymbolAddress((void**)&p, s)
    __nv_bfloat16 *q_hi, *q_lo, *k_hi, *k_lo, *v_hi, *v_lo;
    __nv_bfloat16 *A4_hi, *A4_lo, *B4_hi, *B4_lo, *C4_hi, *C4_lo;
    __nv_bfloat16 *t_hi, *t_lo;
    __half *ZT_h, *at_h;
    float *part;
    SYM(q_hi, g_q_hi);  SYM(q_lo, g_q_lo);
    SYM(k_hi, g_k_hi);  SYM(k_lo, g_k_lo);
    SYM(v_hi, g_v_hi);  SYM(v_lo, g_v_lo);
    SYM(A4_hi, g_A4_hi); SYM(A4_lo, g_A4_lo);
    SYM(B4_hi, g_B4_hi); SYM(B4_lo, g_B4_lo);
    SYM(C4_hi, g_C4_hi); SYM(C4_lo, g_C4_lo);
    SYM(t_hi, g_t_hi);   SYM(t_lo, g_t_lo);
    SYM(ZT_h, g_ZT_h);   SYM(at_h, g_at_h);
    SYM(part, g_part);
#undef SYM

    const long sLD = (long)L_ * D_;
    const long sLL = (long)L_ * L_;
    const long sDD = (long)D_ * D_;
    const long HDD = (long)H_ * D_ * D_;
    const float inv_sqrt_d = 1.0f / sqrtf((float)D_);

    dim3 blk(256);
    const int n4_in = (B_ * L_ * D_) / 4;

    // launch 0: merged q/k/v splits
    dim3 gsp((n4_in + 255) / 256, 3);
    split_qkv<<<gsp, blk>>>((const float4*)q, (const float4*)k, (const float4*)v,
        (uint2*)q_hi, (uint2*)q_lo, (uint2*)k_hi, (uint2*)k_lo,
        (uint2*)v_hi, (uint2*)v_lo, n4_in);

    // launch 1: merged weight prep
    dim3 gtw(D_ / 32, D_ / 32, 4 * H_);
    prep_weights<<<gtw, blk>>>(Wq, Wk, Wv, Wo, A4_hi, A4_lo, B4_hi, B4_lo);

    // launch 2: C4[z] = A4[z] @ B4[z]^T  (256 tiles)
    mma_gemm<1, 2, 2><<<nsm, blk, SMEM_T22>>>(A4_hi, A4_lo, B4_hi, B4_lo,
        nullptr, C4_hi, C4_lo,
        256, 4, 4, D_, D_, D_, D_, sDD, sDD, 1, 2 * H_, 1, 2 * H_, 1, 0, 0,
        1, sDD, 1, 0, 1.0f);

    // launch 3: ZT[b, e, h*L+m] = P[h] @ v[b]^T -> fp16 single limb (1024 tiles)
    mma_gemm<3, 2, 2><<<nsm, blk, SMEM_T22>>>(C4_hi + HDD, C4_lo + HDD, v_hi, v_lo,
        nullptr, (__nv_bfloat16*)ZT_h, nullptr,
        1024, 16, 4, D_, D_, D_, H_ * L_, sDD, sLD, 1, H_, H_, B_, 1, 0, 0,
        H_, (long)D_ * H_ * L_, H_, (long)L_, 1.0f);

    // launch 4: t[b,h] = q[b] @ MT[h]^T   (1024 tiles)
    mma_gemm<1, 2, 2><<<nsm, blk, SMEM_T22>>>(q_hi, q_lo, C4_hi, C4_lo,
        nullptr, t_hi, t_lo,
        1024, 4, 16, D_, D_, D_, D_, sLD, sDD, H_, B_, 1, H_, 1, 0, 0,
        1, sLD, 1, 0, 1.0f);

    // launch 5: scores[b,h] = t[b,h] @ k[b]^T / sqrt(D) (4096 tiles)
    mma_gemm<0, 2, 2><<<nsm, blk, SMEM_T22>>>(t_hi, t_lo, k_hi, k_lo,
        attn, nullptr, nullptr,
        4096, 16, 16, D_, D_, D_, L_, sLD, sLD, 1, B_ * H_, H_, B_, 1, 0, 0,
        1, sLL, 1, 0, inv_sqrt_d);

    // launch 6: softmax in place + fp16 single-limb copy in [b,l,h,m] layout
    softmax_split<<<B_ * H_ * L_, blk>>>(attn, (uint2*)at_h);

    // launch 7: out partials, split-K=4 over H*L, fp16 x fp16 1 MMA (512 tiles)
    mma_gemm<0, 1, 1><<<nsm, blk, SMEM_T11>>>((const __nv_bfloat16*)at_h, nullptr,
        (const __nv_bfloat16*)ZT_h, nullptr,
        part, nullptr, nullptr,
        512, 4, 16, (H_ * L_) / KS_, H_ * L_, H_ * L_, D_,
        (long)L_ * H_ * L_, (long)D_ * H_ * L_, KS_, B_, KS_, B_,
        KS_, (H_ * L_) / KS_, (H_ * L_) / KS_,
        1, sLD, 1, 0, 1.0f);

    // launch 8: reduce partials -> out
    reduce_part<<<(B_ * L_ * D_ / 4) / 256, blk>>>((const float4*)part, (float4*)out);
}

// round 15
// speedup vs baseline: 1.1404x; 1.0070x over previous
#include <cuda_runtime.h>
#include <cuda_bf16.h>
#include <cuda_fp16.h>
#include <stdint.h>
#include <math.h>

#define B_  2
#define L_  2048
#define D_  512
#define H_  8
#define KS_ 4

// ======================= scratch (device globals) ==========================
__device__ __nv_bfloat16 g_q_hi [(size_t)B_*L_*D_];
__device__ __nv_bfloat16 g_q_lo [(size_t)B_*L_*D_];
__device__ __nv_bfloat16 g_k_hi [(size_t)B_*L_*D_];
__device__ __nv_bfloat16 g_k_lo [(size_t)B_*L_*D_];
__device__ __nv_bfloat16 g_v_hi [(size_t)B_*L_*D_];
__device__ __nv_bfloat16 g_v_lo [(size_t)B_*L_*D_];
// concatenated: A4 = [WkT | Wo'], B4 = [WqT | WvT], C4 = [MT | P]
__device__ __nv_bfloat16 g_A4_hi[(size_t)2*H_*D_*D_];
__device__ __nv_bfloat16 g_A4_lo[(size_t)2*H_*D_*D_];
__device__ __nv_bfloat16 g_B4_hi[(size_t)2*H_*D_*D_];
__device__ __nv_bfloat16 g_B4_lo[(size_t)2*H_*D_*D_];
__device__ __nv_bfloat16 g_C4_hi[(size_t)2*H_*D_*D_];
__device__ __nv_bfloat16 g_C4_lo[(size_t)2*H_*D_*D_];
__device__ __nv_bfloat16 g_t_hi [(size_t)B_*H_*L_*D_];
__device__ __nv_bfloat16 g_t_lo [(size_t)B_*H_*L_*D_];
__device__ __half        g_ZT_h [(size_t)B_*D_*H_*L_];   // fp16 single-limb ZT
__device__ __half        g_sc_h [(size_t)B_*H_*L_*L_];   // fp16 raw scores
__device__ __half        g_at_h [(size_t)B_*L_*H_*L_];   // fp16 normalized attn (permuted)
__device__ float         g_part [(size_t)B_*KS_*L_*D_];

// ======================= small helpers ======================================
__device__ __forceinline__ uint32_t smem_u32(const void* p) {
    uint32_t a;
    asm("{ .reg .u64 t; cvta.to.shared.u64 t, %1; cvt.u32.u64 %0, t; }"
        : "=r"(a) : "l"(p));
    return a;
}
__device__ __forceinline__ uint32_t swz128(uint32_t o) { return o ^ ((o >> 3) & 0x70); }

__device__ __forceinline__ void cp16(uint32_t s, const void* g) {
    asm volatile("cp.async.cg.shared.global [%0], [%1], 16;" :: "r"(s), "l"(g));
}
#define CP_COMMIT() asm volatile("cp.async.commit_group;" ::: "memory")

__device__ __forceinline__ void ldm4(uint32_t* r, uint32_t a) {
    asm volatile("ldmatrix.sync.aligned.m8n8.x4.shared.b16 {%0,%1,%2,%3}, [%4];"
                 : "=r"(r[0]), "=r"(r[1]), "=r"(r[2]), "=r"(r[3]) : "r"(a));
}
__device__ __forceinline__ void mma_bf16(float* c, const uint32_t* a, const uint32_t* b) {
    asm volatile("mma.sync.aligned.m16n8k16.row.col.f32.bf16.bf16.f32 "
                 "{%0,%1,%2,%3}, {%4,%5,%6,%7}, {%8,%9}, {%0,%1,%2,%3};"
                 : "+f"(c[0]), "+f"(c[1]), "+f"(c[2]), "+f"(c[3])
                 : "r"(a[0]), "r"(a[1]), "r"(a[2]), "r"(a[3]), "r"(b[0]), "r"(b[1]));
}
__device__ __forceinline__ void mma_f16(float* c, const uint32_t* a, const uint32_t* b) {
    asm volatile("mma.sync.aligned.m16n8k16.row.col.f32.f16.f16.f32 "
                 "{%0,%1,%2,%3}, {%4,%5,%6,%7}, {%8,%9}, {%0,%1,%2,%3};"
                 : "+f"(c[0]), "+f"(c[1]), "+f"(c[2]), "+f"(c[3])
                 : "r"(a[0]), "r"(a[1]), "r"(a[2]), "r"(a[3]), "r"(b[0]), "r"(b[1]));
}
__device__ __forceinline__ void split2(float x, __nv_bfloat16& h, __nv_bfloat16& l) {
    h = __float2bfloat16(x);
    l = __float2bfloat16(x - __bfloat162float(h));
}
__device__ __forceinline__ void split_pack(float2 v, uint32_t& hi, uint32_t& lo) {
    __nv_bfloat16 h0, l0, h1, l1;
    split2(v.x, h0, l0);
    split2(v.y, h1, l1);
    hi = ((uint32_t)__bfloat16_as_ushort(h1) << 16) | __bfloat16_as_ushort(h0);
    lo = ((uint32_t)__bfloat16_as_ushort(l1) << 16) | __bfloat16_as_ushort(l0);
}
__device__ __forceinline__ uint32_t pack_h2(float2 v) {
    __half h0 = __float2half(v.x);
    __half h1 = __float2half(v.y);
    return ((uint32_t)__half_as_ushort(h1) << 16) | __half_as_ushort(h0);
}

// ============ persistent multi-limb HMMA GEMM (KC=64, 3-stage) ==============
// OUT: 0 fp32, 1 bf16 hi/lo pair, 3 fp16 single limb (Chi only)
// AL/BL: limb counts. (2,2)=3 bf16 MMAs; (1,1)=1 f16 MMA.
#define KC       64
#define TILE_B   (128 * 128)

struct TileP {
    const __nv_bfloat16 *ah, *al, *bh, *bl;
    long coff;
};

template <int OUT, int AL, int BL>
__global__ __launch_bounds__(256, 1)
void mma_gemm(const __nv_bfloat16* __restrict__ Ahi, const __nv_bfloat16* __restrict__ Alo,
              const __nv_bfloat16* __restrict__ Bhi, const __nv_bfloat16* __restrict__ Blo,
              float* __restrict__ C, __nv_bfloat16* __restrict__ Chi,
              __nv_bfloat16* __restrict__ Clo,
              int ntiles, int gx, int gy,
              int K, int lda, int ldb, int ldc,
              long sA, long sB, int adiv, int amod, int bdiv, int bmod,
              int azmod, long sA2, long sB2,
              int czdiv, long sC1, int czmod, long sC2, float alpha)
{
    constexpr int ATB = AL * TILE_B;
    constexpr int STB = (AL + BL) * TILE_B;

    extern __shared__ char smem[];
    const uint32_t sb = smem_u32(smem);
    const int tid  = threadIdx.x;
    const int lane = tid & 31, wid = tid >> 5;
    const int moff = (wid & 1) * 64;
    const int noff = (wid >> 1) * 32;

    int t0 = blockIdx.x;
    if (t0 >= ntiles) return;

    auto tileinfo = [&](int t) -> TileP {
        const int gxy = gx * gy;
        const int z = t / gxy;
        const int r = t - z * gxy;
        const int ty = r / gx;
        const int tx = r - ty * gx;
        const long aoff = (long)((z / adiv) % amod) * sA + (long)(z % azmod) * sA2
                          + (long)ty * 128 * lda;
        const long boff = (long)((z / bdiv) % bmod) * sB + (long)(z % azmod) * sB2
                          + (long)tx * 128 * ldb;
        TileP p;
        p.ah = Ahi + aoff;  p.al = Alo + aoff;
        p.bh = Bhi + boff;  p.bl = Blo + boff;
        p.coff = (long)(z / czdiv) * sC1 + (long)(z % czmod) * sC2
                 + (long)ty * 128 * ldc + (long)tx * 128;
        return p;
    };

#define LOADT(T, cidx, stg) do {                                                 \
        const uint32_t st = sb + (stg) * STB;                                    \
        const int k0 = (cidx) * KC;                                              \
        _Pragma("unroll")                                                        \
        for (int it = 0; it < 4; it++) {                                         \
            const int idx = tid + it * 256;                                      \
            const int row = idx >> 3, ch = idx & 7;                              \
            const uint32_t so = swz128(row * 128 + ch * 16);                     \
            const long goA = (long)row * lda + k0 + ch * 8;                      \
            const long goB = (long)row * ldb + k0 + ch * 8;                      \
            cp16(st + so, (T).ah + goA);                                         \
            if (AL == 2) cp16(st + TILE_B + so, (T).al + goA);                   \
            cp16(st + ATB + so, (T).bh + goB);                                   \
            if (BL == 2) cp16(st + ATB + TILE_B + so, (T).bl + goB);             \
        }                                                                        \
    } while (0)

    const int NC = K / KC;
    const int stride = gridDim.x;

    TileP cur = tileinfo(t0);
    LOADT(cur, 0, 0); CP_COMMIT();
    LOADT(cur, 1, 1); CP_COMMIT();
    int lstage = 2;
    int cstage = 0;

    const int arow = (lane & 7) + ((lane >> 3) & 1) * 8;
    const int ach  = (lane >> 4);
    const int brow = (lane & 7) + ((lane >> 4) & 1) * 8;
    const int bch  = ((lane >> 3) & 1);
    const int gq = lane >> 2, tg = lane & 3;

    for (int t = t0; t < ntiles; t += stride) {
        const int tn = t + stride;
        const bool has_next = tn < ntiles;
        TileP nxt = has_next ? tileinfo(tn) : cur;

        float acc[4][4][4];
#pragma unroll
        for (int a = 0; a < 4; a++)
#pragma unroll
            for (int b = 0; b < 4; b++)
#pragma unroll
                for (int c = 0; c < 4; c++) acc[a][b][c] = 0.f;

        for (int c = 0; c < NC; c++) {
            asm volatile("cp.async.wait_group 1;" ::: "memory");
            __syncthreads();
            const int cc = c + 2;
            if (cc < NC) {
                LOADT(cur, cc, lstage);
            } else if (has_next && cc - NC < 2) {
                LOADT(nxt, cc - NC, lstage);
            }
            CP_COMMIT();
            lstage = (lstage == 2) ? 0 : lstage + 1;

            const uint32_t st = sb + cstage * STB;
            cstage = (cstage == 2) ? 0 : cstage + 1;
#pragma unroll
            for (int kk = 0; kk < 4; kk++) {
                uint32_t ah[4][4], al[4][4], bh[4][2], bl[4][2];
#pragma unroll
                for (int mf = 0; mf < 4; mf++) {
                    uint32_t ad = st + swz128((moff + mf * 16 + arow) * 128 + (kk * 2 + ach) * 16);
                    ldm4(ah[mf], ad);
                    if (AL == 2) ldm4(al[mf], ad + TILE_B);
                }
#pragma unroll
                for (int p = 0; p < 2; p++) {
                    uint32_t bd = st + ATB +
                                  swz128((noff + p * 16 + brow) * 128 + (kk * 2 + bch) * 16);
                    uint32_t r[4];
                    ldm4(r, bd);
                    bh[2 * p][0] = r[0]; bh[2 * p][1] = r[1];
                    bh[2 * p + 1][0] = r[2]; bh[2 * p + 1][1] = r[3];
                    if (BL == 2) {
                        ldm4(r, bd + TILE_B);
                        bl[2 * p][0] = r[0]; bl[2 * p][1] = r[1];
                        bl[2 * p + 1][0] = r[2]; bl[2 * p + 1][1] = r[3];
                    }
                }
#pragma unroll
                for (int mf = 0; mf < 4; mf++)
#pragma unroll
                    for (int nf = 0; nf < 4; nf++) {
                        if (AL == 2 && BL == 2) {
                            mma_bf16(acc[mf][nf], ah[mf], bh[nf]);
                            mma_bf16(acc[mf][nf], ah[mf], bl[nf]);
                            mma_bf16(acc[mf][nf], al[mf], bh[nf]);
                        } else {
                            mma_f16(acc[mf][nf], ah[mf], bh[nf]);
                            if (BL == 2) mma_f16(acc[mf][nf], ah[mf], bl[nf]);
                        }
                    }
            }
        }

        // ---- epilogue ----
#pragma unroll
        for (int mf = 0; mf < 4; mf++)
#pragma unroll
            for (int nf = 0; nf < 4; nf++) {
                const long row = moff + mf * 16 + gq;
                const long col = noff + nf * 8 + tg * 2;
                float v0 = alpha * acc[mf][nf][0];
                float v1 = alpha * acc[mf][nf][1];
                float v2 = alpha * acc[mf][nf][2];
                float v3 = alpha * acc[mf][nf][3];
                if (OUT == 0) {
                    float2 p0 = {v0, v1}, p1 = {v2, v3};
                    *reinterpret_cast<float2*>(C + cur.coff + row * ldc + col)       = p0;
                    *reinterpret_cast<float2*>(C + cur.coff + (row + 8) * ldc + col) = p1;
                } else if (OUT == 1) {
                    uint32_t hp0, lp0, hp1, lp1;
                    split_pack({v0, v1}, hp0, lp0);
                    split_pack({v2, v3}, hp1, lp1);
                    *reinterpret_cast<uint32_t*>(Chi + cur.coff + row * ldc + col)       = hp0;
                    *reinterpret_cast<uint32_t*>(Clo + cur.coff + row * ldc + col)       = lp0;
                    *reinterpret_cast<uint32_t*>(Chi + cur.coff + (row + 8) * ldc + col) = hp1;
                    *reinterpret_cast<uint32_t*>(Clo + cur.coff + (row + 8) * ldc + col) = lp1;
                } else {   // OUT == 3: single fp16 limb
                    *reinterpret_cast<uint32_t*>(Chi + cur.coff + row * ldc + col)       = pack_h2({v0, v1});
                    *reinterpret_cast<uint32_t*>(Chi + cur.coff + (row + 8) * ldc + col) = pack_h2({v2, v3});
                }
            }
        cur = nxt;
    }
#undef LOADT
}

#define SMEM_T22 (3 * 4 * TILE_B)   // (2,2): 192 KB
#define SMEM_T11 (3 * 2 * TILE_B)   // (1,1): 96 KB

// ======================= helper kernels =====================================
__global__ __launch_bounds__(256)
void split_qkv(const float4* __restrict__ q, const float4* __restrict__ k,
               const float4* __restrict__ v,
               uint2* __restrict__ qh, uint2* __restrict__ ql,
               uint2* __restrict__ kh, uint2* __restrict__ kl,
               uint2* __restrict__ vh, uint2* __restrict__ vl, int n4)
{
    int i = blockIdx.x * 256 + threadIdx.x;
    if (i >= n4) return;
    const int sel = blockIdx.y;
    const float4* s = (sel == 0) ? q : (sel == 1) ? k : v;
    uint2* hi = (sel == 0) ? qh : (sel == 1) ? kh : vh;
    uint2* lo = (sel == 0) ? ql : (sel == 1) ? kl : vl;
    float4 x = s[i];
    __nv_bfloat16 h[4], l[4];
    split2(x.x, h[0], l[0]);
    split2(x.y, h[1], l[1]);
    split2(x.z, h[2], l[2]);
    split2(x.w, h[3], l[3]);
    hi[i] = *reinterpret_cast<uint2*>(h);
    lo[i] = *reinterpret_cast<uint2*>(l);
}

// merged weight prep: zz = w*8 + h; w<3 transpose-split, w==3 Wo permute-split
__global__ __launch_bounds__(256)
void prep_weights(const float* __restrict__ Wq, const float* __restrict__ Wk,
                  const float* __restrict__ Wv, const float* __restrict__ Wo,
                  __nv_bfloat16* __restrict__ A4hi, __nv_bfloat16* __restrict__ A4lo,
                  __nv_bfloat16* __restrict__ B4hi, __nv_bfloat16* __restrict__ B4lo)
{
    __shared__ float t[32][33];
    const int zz = blockIdx.z;
    const int w = zz >> 3, z = zz & 7;
    const long HDD = (long)H_ * D_ * D_;
    const int tx = threadIdx.x & 31, ty = threadIdx.x >> 5;

    if (w == 3) {
        const int e0 = blockIdx.y * 32, f0 = blockIdx.x * 32;
        const long base = HDD + (long)z * D_ * D_;
#pragma unroll
        for (int r = 0; r < 32; r += 8) {
            const int e = e0 + ty + r, f = f0 + tx;
            float x = Wo[(long)e * (H_ * D_) + (f >> 6) * 512 + z * 64 + (f & 63)];
            __nv_bfloat16 h, l;
            split2(x, h, l);
            long o = base + (long)e * D_ + f;
            A4hi[o] = h; A4lo[o] = l;
        }
        return;
    }

    const float* src = (w == 0) ? Wq : (w == 1) ? Wk : Wv;
    __nv_bfloat16* hi = (w == 0) ? B4hi : (w == 1) ? A4hi : (B4hi + HDD);
    __nv_bfloat16* lo = (w == 0) ? B4lo : (w == 1) ? A4lo : (B4lo + HDD);

    const int e0 = blockIdx.y * 32, d0 = blockIdx.x * 32;
    const float* s = src + (long)z * D_ * D_;
#pragma unroll
    for (int r = 0; r < 32; r += 8)
        t[ty + r][tx] = s[(long)(e0 + ty + r) * D_ + d0 + tx];
    __syncthreads();
    const long base = (long)z * D_ * D_;
#pragma unroll
    for (int r = 0; r < 32; r += 8) {
        float x = t[tx][ty + r];
        __nv_bfloat16 h, l;
        split2(x, h, l);
        long o = base + (long)(d0 + ty + r) * D_ + e0 + tx;
        hi[o] = h; lo[o] = l;
    }
}

// softmax: read fp16 raw scores [b,h,l,m], write fp32 normalized attn (d_out)
// + fp16 normalized copy in [b,l,h,m]. One block per row; thread = 8 elems (uint4).
__global__ __launch_bounds__(256)
void softmax_h(const uint4* __restrict__ sc, float4* __restrict__ attn,
               uint4* __restrict__ at)
{
    const int r = blockIdx.x;                 // (b*H + h)*L + l
    const int b = r >> 14;
    const int h = (r >> 11) & (H_ - 1);
    const int l = r & (L_ - 1);
    const int tid = threadIdx.x;

    // load 8 halfs
    uint4 raw = sc[(long)r * (L_ / 8) + tid];
    __half2 h2[4];
    h2[0] = *reinterpret_cast<__half2*>(&raw.x);
    h2[1] = *reinterpret_cast<__half2*>(&raw.y);
    h2[2] = *reinterpret_cast<__half2*>(&raw.z);
    h2[3] = *reinterpret_cast<__half2*>(&raw.w);
    float v[8];
#pragma unroll
    for (int i = 0; i < 4; i++) {
        float2 f = __half22float2(h2[i]);
        v[2 * i] = f.x;
        v[2 * i + 1] = f.y;
    }

    float vmax = -1e30f;
#pragma unroll
    for (int i = 0; i < 8; i++) vmax = fmaxf(vmax, v[i]);
#pragma unroll
    for (int o = 16; o > 0; o >>= 1) vmax = fmaxf(vmax, __shfl_xor_sync(0xFFFFFFFFu, vmax, o));

    __shared__ float smax[8], ssum[8];
    if ((tid & 31) == 0) smax[tid >> 5] = vmax;
    __syncthreads();
    float m = smax[0];
#pragma unroll
    for (int i = 1; i < 8; i++) m = fmaxf(m, smax[i]);

    float sum = 0.f;
#pragma unroll
    for (int i = 0; i < 8; i++) { v[i] = __expf(v[i] - m); sum += v[i]; }
#pragma unroll
    for (int o = 16; o > 0; o >>= 1) sum += __shfl_xor_sync(0xFFFFFFFFu, sum, o);
    if ((tid & 31) == 0) ssum[tid >> 5] = sum;
    __syncthreads();
    float tot = 0.f;
#pragma unroll
    for (int i = 0; i < 8; i++) tot += ssum[i];
    const float inv = 1.f / tot;

#pragma unroll
    for (int i = 0; i < 8; i++) v[i] *= inv;

    // fp32 normalized -> attn region (row-contiguous)
    float4* arow = attn + (long)r * (L_ / 4);
    float4 f0 = {v[0], v[1], v[2], v[3]};
    float4 f1 = {v[4], v[5], v[6], v[7]};
    arow[2 * tid]     = f0;
    arow[2 * tid + 1] = f1;

    // fp16 normalized -> at[b,l,h,m]
    uint4 hp;
    hp.x = pack_h2({v[0], v[1]});
    hp.y = pack_h2({v[2], v[3]});
    hp.z = pack_h2({v[4], v[5]});
    hp.w = pack_h2({v[6], v[7]});
    const long ob = ((((long)b * L_ + l) * H_ + h) * L_) >> 3;
    at[ob + tid] = hp;
}

// reduce partials: out[b][j] = sum_ks part[b*KS+ks][j]
__global__ __launch_bounds__(256)
void reduce_part(const float4* __restrict__ part, float4* __restrict__ out)
{
    const int LD4 = L_ * D_ / 4;
    long idx = (long)blockIdx.x * 256 + threadIdx.x;
    int b = (int)(idx / LD4);
    long j = idx - (long)b * LD4;
    const float4* p = part + (long)b * KS_ * LD4 + j;
    float4 s = p[0];
#pragma unroll
    for (int ks = 1; ks < KS_; ks++) {
        float4 t = p[(long)ks * LD4];
        s.x += t.x; s.y += t.y; s.z += t.z; s.w += t.w;
    }
    out[idx] = s;
}

// ======================= launch =============================================
extern "C" void kernel_launch(void* const* d_in, const int* in_sizes, int n_in,
                              void* d_out, int out_size)
{
    const float* q  = (const float*)d_in[0];
    const float* k  = (const float*)d_in[1];
    const float* v  = (const float*)d_in[2];
    const float* Wq = (const float*)d_in[3];
    const float* Wk = (const float*)d_in[4];
    const float* Wv = (const float*)d_in[5];
    const float* Wo = (const float*)d_in[6];

    float* out  = (float*)d_out;
    float* attn = out + (long)B_ * L_ * D_;

    static int nsm = 0;
    if (!nsm) {
        cudaDeviceGetAttribute(&nsm, cudaDevAttrMultiProcessorCount, 0);
        cudaFuncSetAttribute((const void*)mma_gemm<1, 2, 2>, cudaFuncAttributeMaxDynamicSharedMemorySize, SMEM_T22);
        cudaFuncSetAttribute((const void*)mma_gemm<3, 2, 2>, cudaFuncAttributeMaxDynamicSharedMemorySize, SMEM_T22);
        cudaFuncSetAttribute((const void*)mma_gemm<0, 1, 1>, cudaFuncAttributeMaxDynamicSharedMemorySize, SMEM_T11);
        if (nsm <= 0) nsm = 148;
    }

#define SYM(p, s) cudaGetSymbolAddress((void**)&p, s)
    __nv_bfloat16 *q_hi, *q_lo, *k_hi, *k_lo, *v_hi, *v_lo;
    __nv_bfloat16 *A4_hi, *A4_lo, *B4_hi, *B4_lo, *C4_hi, *C4_lo;
    __nv_bfloat16 *t_hi, *t_lo;
    __half *ZT_h, *sc_h, *at_h;
    float *part;
    SYM(q_hi, g_q_hi);  SYM(q_lo, g_q_lo);
    SYM(k_hi, g_k_hi);  SYM(k_lo, g_k_lo);
    SYM(v_hi, g_v_hi);  SYM(v_lo, g_v_lo);
    SYM(A4_hi, g_A4_hi); SYM(A4_lo, g_A4_lo);
    SYM(B4_hi, g_B4_hi); SYM(B4_lo, g_B4_lo);
    SYM(C4_hi, g_C4_hi); SYM(C4_lo, g_C4_lo);
    SYM(t_hi, g_t_hi);   SYM(t_lo, g_t_lo);
    SYM(ZT_h, g_ZT_h);   SYM(sc_h, g_sc_h);  SYM(at_h, g_at_h);
    SYM(part, g_part);
#undef SYM

    const long sLD = (long)L_ * D_;
    const long sLL = (long)L_ * L_;
    const long sDD = (long)D_ * D_;
    const long HDD = (long)H_ * D_ * D_;
    const float inv_sqrt_d = 1.0f / sqrtf((float)D_);

    dim3 blk(256);
    const int n4_in = (B_ * L_ * D_) / 4;

    // launch 0: merged q/k/v splits
    dim3 gsp((n4_in + 255) / 256, 3);
    split_qkv<<<gsp, blk>>>((const float4*)q, (const float4*)k, (const float4*)v,
        (uint2*)q_hi, (uint2*)q_lo, (uint2*)k_hi, (uint2*)k_lo,
        (uint2*)v_hi, (uint2*)v_lo, n4_in);

    // launch 1: merged weight prep
    dim3 gtw(D_ / 32, D_ / 32, 4 * H_);
    prep_weights<<<gtw, blk>>>(Wq, Wk, Wv, Wo, A4_hi, A4_lo, B4_hi, B4_lo);

    // launch 2: C4[z] = A4[z] @ B4[z]^T  (256 tiles)
    mma_gemm<1, 2, 2><<<nsm, blk, SMEM_T22>>>(A4_hi, A4_lo, B4_hi, B4_lo,
        nullptr, C4_hi, C4_lo,
        256, 4, 4, D_, D_, D_, D_, sDD, sDD, 1, 2 * H_, 1, 2 * H_, 1, 0, 0,
        1, sDD, 1, 0, 1.0f);

    // launch 3: ZT[b, e, h*L+m] = P[h] @ v[b]^T -> fp16 single limb (1024 tiles)
    mma_gemm<3, 2, 2><<<nsm, blk, SMEM_T22>>>(C4_hi + HDD, C4_lo + HDD, v_hi, v_lo,
        nullptr, (__nv_bfloat16*)ZT_h, nullptr,
        1024, 16, 4, D_, D_, D_, H_ * L_, sDD, sLD, 1, H_, H_, B_, 1, 0, 0,
        H_, (long)D_ * H_ * L_, H_, (long)L_, 1.0f);

    // launch 4: t[b,h] = q[b] @ MT[h]^T   (1024 tiles)
    mma_gemm<1, 2, 2><<<nsm, blk, SMEM_T22>>>(q_hi, q_lo, C4_hi, C4_lo,
        nullptr, t_hi, t_lo,
        1024, 4, 16, D_, D_, D_, D_, sLD, sDD, H_, B_, 1, H_, 1, 0, 0,
        1, sLD, 1, 0, 1.0f);

    // launch 5: scores[b,h] = t[b,h] @ k[b]^T / sqrt(D) -> fp16 raw (4096 tiles)
    mma_gemm<3, 2, 2><<<nsm, blk, SMEM_T22>>>(t_hi, t_lo, k_hi, k_lo,
        nullptr, (__nv_bfloat16*)sc_h, nullptr,
        4096, 16, 16, D_, D_, D_, L_, sLD, sLD, 1, B_ * H_, H_, B_, 1, 0, 0,
        1, sLL, 1, 0, inv_sqrt_d);

    // launch 6: softmax from fp16 raw -> fp32 attn (d_out) + fp16 copy [b,l,h,m]
    softmax_h<<<B_ * H_ * L_, blk>>>((const uint4*)sc_h, (float4*)attn, (uint4*)at_h);

    // launch 7: out partials, split-K=4 over H*L, fp16 x fp16 1 MMA (512 tiles)
    mma_gemm<0, 1, 1><<<nsm, blk, SMEM_T11>>>((const __nv_bfloat16*)at_h, nullptr,
        (const __nv_bfloat16*)ZT_h, nullptr,
        part, nullptr, nullptr,
        512, 4, 16, (H_ * L_) / KS_, H_ * L_, H_ * L_, D_,
        (long)L_ * H_ * L_, (long)D_ * H_ * L_, KS_, B_, KS_, B_,
        KS_, (H_ * L_) / KS_, (H_ * L_) / KS_,
        1, sLD, 1, 0, 1.0f);

    // launch 8: reduce partials -> out
    reduce_part<<<(B_ * L_ * D_ / 4) / 256, blk>>>((const float4*)part, (float4*)out);
}

// round 16
// speedup vs baseline: 1.7757x; 1.5572x over previous
#include <cuda_runtime.h>
#include <cuda_bf16.h>
#include <cuda_fp16.h>
#include <stdint.h>
#include <math.h>

#define B_  2
#define L_  2048
#define D_  512
#define H_  8
#define KS_ 4

// ======================= scratch (device globals) ==========================
__device__ __half        g_q_h [(size_t)B_*L_*D_];
__device__ __half        g_k_h [(size_t)B_*L_*D_];
__device__ __half        g_v_h [(size_t)B_*L_*D_];
// concatenated: A4 = [WkT | Wo'], B4 = [WqT | WvT] (bf16 2-limb), C4_h = [MT | P] fp16
__device__ __nv_bfloat16 g_A4_hi[(size_t)2*H_*D_*D_];
__device__ __nv_bfloat16 g_A4_lo[(size_t)2*H_*D_*D_];
__device__ __nv_bfloat16 g_B4_hi[(size_t)2*H_*D_*D_];
__device__ __nv_bfloat16 g_B4_lo[(size_t)2*H_*D_*D_];
__device__ __half        g_C4_h [(size_t)2*H_*D_*D_];
__device__ __half        g_t_h  [(size_t)B_*H_*L_*D_];
__device__ __half        g_ZT_h [(size_t)B_*D_*H_*L_];
__device__ __half        g_sc_h [(size_t)B_*H_*L_*L_];
__device__ __half        g_at_h [(size_t)B_*L_*H_*L_];
__device__ float         g_part [(size_t)B_*KS_*L_*D_];

// ======================= small helpers ======================================
__device__ __forceinline__ uint32_t smem_u32(const void* p) {
    uint32_t a;
    asm("{ .reg .u64 t; cvta.to.shared.u64 t, %1; cvt.u32.u64 %0, t; }"
        : "=r"(a) : "l"(p));
    return a;
}
__device__ __forceinline__ uint32_t swz128(uint32_t o) { return o ^ ((o >> 3) & 0x70); }

__device__ __forceinline__ void cp16(uint32_t s, const void* g) {
    asm volatile("cp.async.cg.shared.global [%0], [%1], 16;" :: "r"(s), "l"(g));
}
#define CP_COMMIT() asm volatile("cp.async.commit_group;" ::: "memory")

__device__ __forceinline__ void ldm4(uint32_t* r, uint32_t a) {
    asm volatile("ldmatrix.sync.aligned.m8n8.x4.shared.b16 {%0,%1,%2,%3}, [%4];"
                 : "=r"(r[0]), "=r"(r[1]), "=r"(r[2]), "=r"(r[3]) : "r"(a));
}
__device__ __forceinline__ void mma_bf16(float* c, const uint32_t* a, const uint32_t* b) {
    asm volatile("mma.sync.aligned.m16n8k16.row.col.f32.bf16.bf16.f32 "
                 "{%0,%1,%2,%3}, {%4,%5,%6,%7}, {%8,%9}, {%0,%1,%2,%3};"
                 : "+f"(c[0]), "+f"(c[1]), "+f"(c[2]), "+f"(c[3])
                 : "r"(a[0]), "r"(a[1]), "r"(a[2]), "r"(a[3]), "r"(b[0]), "r"(b[1]));
}
__device__ __forceinline__ void mma_f16(float* c, const uint32_t* a, const uint32_t* b) {
    asm volatile("mma.sync.aligned.m16n8k16.row.col.f32.f16.f16.f32 "
                 "{%0,%1,%2,%3}, {%4,%5,%6,%7}, {%8,%9}, {%0,%1,%2,%3};"
                 : "+f"(c[0]), "+f"(c[1]), "+f"(c[2]), "+f"(c[3])
                 : "r"(a[0]), "r"(a[1]), "r"(a[2]), "r"(a[3]), "r"(b[0]), "r"(b[1]));
}
__device__ __forceinline__ void split2(float x, __nv_bfloat16& h, __nv_bfloat16& l) {
    h = __float2bfloat16(x);
    l = __float2bfloat16(x - __bfloat162float(h));
}
__device__ __forceinline__ void split_pack(float2 v, uint32_t& hi, uint32_t& lo) {
    __nv_bfloat16 h0, l0, h1, l1;
    split2(v.x, h0, l0);
    split2(v.y, h1, l1);
    hi = ((uint32_t)__bfloat16_as_ushort(h1) << 16) | __bfloat16_as_ushort(h0);
    lo = ((uint32_t)__bfloat16_as_ushort(l1) << 16) | __bfloat16_as_ushort(l0);
}
__device__ __forceinline__ uint32_t pack_h2(float2 v) {
    __half h0 = __float2half(v.x);
    __half h1 = __float2half(v.y);
    return ((uint32_t)__half_as_ushort(h1) << 16) | __half_as_ushort(h0);
}

// ============ persistent multi-limb HMMA GEMM (KC=64, 3-stage) ==============
// OUT: 0 fp32, 1 bf16 hi/lo pair, 3 fp16 single limb (Chi only)
// AL/BL: limb counts. (2,2)=3 bf16 MMAs; (1,1)=1 f16 MMA.
#define KC       64
#define TILE_B   (128 * 128)

struct TileP {
    const __nv_bfloat16 *ah, *al, *bh, *bl;
    long coff;
};

template <int OUT, int AL, int BL>
__global__ __launch_bounds__(256, 1)
void mma_gemm(const __nv_bfloat16* __restrict__ Ahi, const __nv_bfloat16* __restrict__ Alo,
              const __nv_bfloat16* __restrict__ Bhi, const __nv_bfloat16* __restrict__ Blo,
              float* __restrict__ C, __nv_bfloat16* __restrict__ Chi,
              __nv_bfloat16* __restrict__ Clo,
              int ntiles, int gx, int gy,
              int K, int lda, int ldb, int ldc,
              long sA, long sB, int adiv, int amod, int bdiv, int bmod,
              int azmod, long sA2, long sB2,
              int czdiv, long sC1, int czmod, long sC2, float alpha)
{
    constexpr int ATB = AL * TILE_B;
    constexpr int STB = (AL + BL) * TILE_B;

    extern __shared__ char smem[];
    const uint32_t sb = smem_u32(smem);
    const int tid  = threadIdx.x;
    const int lane = tid & 31, wid = tid >> 5;
    const int moff = (wid & 1) * 64;
    const int noff = (wid >> 1) * 32;

    int t0 = blockIdx.x;
    if (t0 >= ntiles) return;

    auto tileinfo = [&](int t) -> TileP {
        const int gxy = gx * gy;
        const int z = t / gxy;
        const int r = t - z * gxy;
        const int ty = r / gx;
        const int tx = r - ty * gx;
        const long aoff = (long)((z / adiv) % amod) * sA + (long)(z % azmod) * sA2
                          + (long)ty * 128 * lda;
        const long boff = (long)((z / bdiv) % bmod) * sB + (long)(z % azmod) * sB2
                          + (long)tx * 128 * ldb;
        TileP p;
        p.ah = Ahi + aoff;  p.al = Alo + aoff;
        p.bh = Bhi + boff;  p.bl = Blo + boff;
        p.coff = (long)(z / czdiv) * sC1 + (long)(z % czmod) * sC2
                 + (long)ty * 128 * ldc + (long)tx * 128;
        return p;
    };

#define LOADT(T, cidx, stg) do {                                                 \
        const uint32_t st = sb + (stg) * STB;                                    \
        const int k0 = (cidx) * KC;                                              \
        _Pragma("unroll")                                                        \
        for (int it = 0; it < 4; it++) {                                         \
            const int idx = tid + it * 256;                                      \
            const int row = idx >> 3, ch = idx & 7;                              \
            const uint32_t so = swz128(row * 128 + ch * 16);                     \
            const long goA = (long)row * lda + k0 + ch * 8;                      \
            const long goB = (long)row * ldb + k0 + ch * 8;                      \
            cp16(st + so, (T).ah + goA);                                         \
            if (AL == 2) cp16(st + TILE_B + so, (T).al + goA);                   \
            cp16(st + ATB + so, (T).bh + goB);                                   \
            if (BL == 2) cp16(st + ATB + TILE_B + so, (T).bl + goB);             \
        }                                                                        \
    } while (0)

    const int NC = K / KC;
    const int stride = gridDim.x;

    TileP cur = tileinfo(t0);
    LOADT(cur, 0, 0); CP_COMMIT();
    LOADT(cur, 1, 1); CP_COMMIT();
    int lstage = 2;
    int cstage = 0;

    const int arow = (lane & 7) + ((lane >> 3) & 1) * 8;
    const int ach  = (lane >> 4);
    const int brow = (lane & 7) + ((lane >> 4) & 1) * 8;
    const int bch  = ((lane >> 3) & 1);
    const int gq = lane >> 2, tg = lane & 3;

    for (int t = t0; t < ntiles; t += stride) {
        const int tn = t + stride;
        const bool has_next = tn < ntiles;
        TileP nxt = has_next ? tileinfo(tn) : cur;

        float acc[4][4][4];
#pragma unroll
        for (int a = 0; a < 4; a++)
#pragma unroll
            for (int b = 0; b < 4; b++)
#pragma unroll
                for (int c = 0; c < 4; c++) acc[a][b][c] = 0.f;

        for (int c = 0; c < NC; c++) {
            asm volatile("cp.async.wait_group 1;" ::: "memory");
            __syncthreads();
            const int cc = c + 2;
            if (cc < NC) {
                LOADT(cur, cc, lstage);
            } else if (has_next && cc - NC < 2) {
                LOADT(nxt, cc - NC, lstage);
            }
            CP_COMMIT();
            lstage = (lstage == 2) ? 0 : lstage + 1;

            const uint32_t st = sb + cstage * STB;
            cstage = (cstage == 2) ? 0 : cstage + 1;
#pragma unroll
            for (int kk = 0; kk < 4; kk++) {
                uint32_t ah[4][4], al[4][4], bh[4][2], bl[4][2];
#pragma unroll
                for (int mf = 0; mf < 4; mf++) {
                    uint32_t ad = st + swz128((moff + mf * 16 + arow) * 128 + (kk * 2 + ach) * 16);
                    ldm4(ah[mf], ad);
                    if (AL == 2) ldm4(al[mf], ad + TILE_B);
                }
#pragma unroll
                for (int p = 0; p < 2; p++) {
                    uint32_t bd = st + ATB +
                                  swz128((noff + p * 16 + brow) * 128 + (kk * 2 + bch) * 16);
                    uint32_t r[4];
                    ldm4(r, bd);
                    bh[2 * p][0] = r[0]; bh[2 * p][1] = r[1];
                    bh[2 * p + 1][0] = r[2]; bh[2 * p + 1][1] = r[3];
                    if (BL == 2) {
                        ldm4(r, bd + TILE_B);
                        bl[2 * p][0] = r[0]; bl[2 * p][1] = r[1];
                        bl[2 * p + 1][0] = r[2]; bl[2 * p + 1][1] = r[3];
                    }
                }
#pragma unroll
                for (int mf = 0; mf < 4; mf++)
#pragma unroll
                    for (int nf = 0; nf < 4; nf++) {
                        if (AL == 2 && BL == 2) {
                            mma_bf16(acc[mf][nf], ah[mf], bh[nf]);
                            mma_bf16(acc[mf][nf], ah[mf], bl[nf]);
                            mma_bf16(acc[mf][nf], al[mf], bh[nf]);
                        } else {
                            mma_f16(acc[mf][nf], ah[mf], bh[nf]);
                            if (BL == 2) mma_f16(acc[mf][nf], ah[mf], bl[nf]);
                        }
                    }
            }
        }

        // ---- epilogue ----
#pragma unroll
        for (int mf = 0; mf < 4; mf++)
#pragma unroll
            for (int nf = 0; nf < 4; nf++) {
                const long row = moff + mf * 16 + gq;
                const long col = noff + nf * 8 + tg * 2;
                float v0 = alpha * acc[mf][nf][0];
                float v1 = alpha * acc[mf][nf][1];
                float v2 = alpha * acc[mf][nf][2];
                float v3 = alpha * acc[mf][nf][3];
                if (OUT == 0) {
                    float2 p0 = {v0, v1}, p1 = {v2, v3};
                    *reinterpret_cast<float2*>(C + cur.coff + row * ldc + col)       = p0;
                    *reinterpret_cast<float2*>(C + cur.coff + (row + 8) * ldc + col) = p1;
                } else if (OUT == 1) {
                    uint32_t hp0, lp0, hp1, lp1;
                    split_pack({v0, v1}, hp0, lp0);
                    split_pack({v2, v3}, hp1, lp1);
                    *reinterpret_cast<uint32_t*>(Chi + cur.coff + row * ldc + col)       = hp0;
                    *reinterpret_cast<uint32_t*>(Clo + cur.coff + row * ldc + col)       = lp0;
                    *reinterpret_cast<uint32_t*>(Chi + cur.coff + (row + 8) * ldc + col) = hp1;
                    *reinterpret_cast<uint32_t*>(Clo + cur.coff + (row + 8) * ldc + col) = lp1;
                } else {   // OUT == 3: single fp16 limb
                    *reinterpret_cast<uint32_t*>(Chi + cur.coff + row * ldc + col)       = pack_h2({v0, v1});
                    *reinterpret_cast<uint32_t*>(Chi + cur.coff + (row + 8) * ldc + col) = pack_h2({v2, v3});
                }
            }
        cur = nxt;
    }
#undef LOADT
}

#define SMEM_T22 (3 * 4 * TILE_B)   // (2,2): 192 KB
#define SMEM_T11 (3 * 2 * TILE_B)   // (1,1): 96 KB

// ======================= helper kernels =====================================
// q/k/v -> fp16 single limb
__global__ __launch_bounds__(256)
void split_qkv_h(const float4* __restrict__ q, const float4* __restrict__ k,
                 const float4* __restrict__ v,
                 uint2* __restrict__ qh, uint2* __restrict__ kh,
                 uint2* __restrict__ vh, int n4)
{
    int i = blockIdx.x * 256 + threadIdx.x;
    if (i >= n4) return;
    const int sel = blockIdx.y;
    const float4* s = (sel == 0) ? q : (sel == 1) ? k : v;
    uint2* dst = (sel == 0) ? qh : (sel == 1) ? kh : vh;
    float4 x = s[i];
    uint2 o;
    o.x = pack_h2({x.x, x.y});
    o.y = pack_h2({x.z, x.w});
    dst[i] = o;
}

// merged weight prep: zz = w*8 + h; w<3 transpose-split, w==3 Wo permute-split
__global__ __launch_bounds__(256)
void prep_weights(const float* __restrict__ Wq, const float* __restrict__ Wk,
                  const float* __restrict__ Wv, const float* __restrict__ Wo,
                  __nv_bfloat16* __restrict__ A4hi, __nv_bfloat16* __restrict__ A4lo,
                  __nv_bfloat16* __restrict__ B4hi, __nv_bfloat16* __restrict__ B4lo)
{
    __shared__ float t[32][33];
    const int zz = blockIdx.z;
    const int w = zz >> 3, z = zz & 7;
    const long HDD = (long)H_ * D_ * D_;
    const int tx = threadIdx.x & 31, ty = threadIdx.x >> 5;

    if (w == 3) {
        const int e0 = blockIdx.y * 32, f0 = blockIdx.x * 32;
        const long base = HDD + (long)z * D_ * D_;
#pragma unroll
        for (int r = 0; r < 32; r += 8) {
            const int e = e0 + ty + r, f = f0 + tx;
            float x = Wo[(long)e * (H_ * D_) + (f >> 6) * 512 + z * 64 + (f & 63)];
            __nv_bfloat16 h, l;
            split2(x, h, l);
            long o = base + (long)e * D_ + f;
            A4hi[o] = h; A4lo[o] = l;
        }
        return;
    }

    const float* src = (w == 0) ? Wq : (w == 1) ? Wk : Wv;
    __nv_bfloat16* hi = (w == 0) ? B4hi : (w == 1) ? A4hi : (B4hi + HDD);
    __nv_bfloat16* lo = (w == 0) ? B4lo : (w == 1) ? A4lo : (B4lo + HDD);

    const int e0 = blockIdx.y * 32, d0 = blockIdx.x * 32;
    const float* s = src + (long)z * D_ * D_;
#pragma unroll
    for (int r = 0; r < 32; r += 8)
        t[ty + r][tx] = s[(long)(e0 + ty + r) * D_ + d0 + tx];
    __syncthreads();
    const long base = (long)z * D_ * D_;
#pragma unroll
    for (int r = 0; r < 32; r += 8) {
        float x = t[tx][ty + r];
        __nv_bfloat16 h, l;
        split2(x, h, l);
        long o = base + (long)(d0 + ty + r) * D_ + e0 + tx;
        hi[o] = h; lo[o] = l;
    }
}

// softmax: read fp16 raw scores [b,h,l,m], write fp32 normalized attn (d_out)
// + fp16 normalized copy in [b,l,h,m].
__global__ __launch_bounds__(256)
void softmax_h(const uint4* __restrict__ sc, float4* __restrict__ attn,
               uint4* __restrict__ at)
{
    const int r = blockIdx.x;
    const int b = r >> 14;
    const int h = (r >> 11) & (H_ - 1);
    const int l = r & (L_ - 1);
    const int tid = threadIdx.x;

    uint4 raw = sc[(long)r * (L_ / 8) + tid];
    __half2 h2[4];
    h2[0] = *reinterpret_cast<__half2*>(&raw.x);
    h2[1] = *reinterpret_cast<__half2*>(&raw.y);
    h2[2] = *reinterpret_cast<__half2*>(&raw.z);
    h2[3] = *reinterpret_cast<__half2*>(&raw.w);
    float v[8];
#pragma unroll
    for (int i = 0; i < 4; i++) {
        float2 f = __half22float2(h2[i]);
        v[2 * i] = f.x;
        v[2 * i + 1] = f.y;
    }

    float vmax = -1e30f;
#pragma unroll
    for (int i = 0; i < 8; i++) vmax = fmaxf(vmax, v[i]);
#pragma unroll
    for (int o = 16; o > 0; o >>= 1) vmax = fmaxf(vmax, __shfl_xor_sync(0xFFFFFFFFu, vmax, o));

    __shared__ float smax[8], ssum[8];
    if ((tid & 31) == 0) smax[tid >> 5] = vmax;
    __syncthreads();
    float m = smax[0];
#pragma unroll
    for (int i = 1; i < 8; i++) m = fmaxf(m, smax[i]);

    float sum = 0.f;
#pragma unroll
    for (int i = 0; i < 8; i++) { v[i] = __expf(v[i] - m); sum += v[i]; }
#pragma unroll
    for (int o = 16; o > 0; o >>= 1) sum += __shfl_xor_sync(0xFFFFFFFFu, sum, o);
    if ((tid & 31) == 0) ssum[tid >> 5] = sum;
    __syncthreads();
    float tot = 0.f;
#pragma unroll
    for (int i = 0; i < 8; i++) tot += ssum[i];
    const float inv = 1.f / tot;

#pragma unroll
    for (int i = 0; i < 8; i++) v[i] *= inv;

    float4* arow = attn + (long)r * (L_ / 4);
    float4 f0 = {v[0], v[1], v[2], v[3]};
    float4 f1 = {v[4], v[5], v[6], v[7]};
    arow[2 * tid]     = f0;
    arow[2 * tid + 1] = f1;

    uint4 hp;
    hp.x = pack_h2({v[0], v[1]});
    hp.y = pack_h2({v[2], v[3]});
    hp.z = pack_h2({v[4], v[5]});
    hp.w = pack_h2({v[6], v[7]});
    const long ob = ((((long)b * L_ + l) * H_ + h) * L_) >> 3;
    at[ob + tid] = hp;
}

// reduce partials: out[b][j] = sum_ks part[b*KS+ks][j]
__global__ __launch_bounds__(256)
void reduce_part(const float4* __restrict__ part, float4* __restrict__ out)
{
    const int LD4 = L_ * D_ / 4;
    long idx = (long)blockIdx.x * 256 + threadIdx.x;
    int b = (int)(idx / LD4);
    long j = idx - (long)b * LD4;
    const float4* p = part + (long)b * KS_ * LD4 + j;
    float4 s = p[0];
#pragma unroll
    for (int ks = 1; ks < KS_; ks++) {
        float4 t = p[(long)ks * LD4];
        s.x += t.x; s.y += t.y; s.z += t.z; s.w += t.w;
    }
    out[idx] = s;
}

// ======================= launch =============================================
extern "C" void kernel_launch(void* const* d_in, const int* in_sizes, int n_in,
                              void* d_out, int out_size)
{
    const float* q  = (const float*)d_in[0];
    const float* k  = (const float*)d_in[1];
    const float* v  = (const float*)d_in[2];
    const float* Wq = (const float*)d_in[3];
    const float* Wk = (const float*)d_in[4];
    const float* Wv = (const float*)d_in[5];
    const float* Wo = (const float*)d_in[6];

    float* out  = (float*)d_out;
    float* attn = out + (long)B_ * L_ * D_;

    static int nsm = 0;
    if (!nsm) {
        cudaDeviceGetAttribute(&nsm, cudaDevAttrMultiProcessorCount, 0);
        cudaFuncSetAttribute((const void*)mma_gemm<3, 2, 2>, cudaFuncAttributeMaxDynamicSharedMemorySize, SMEM_T22);
        cudaFuncSetAttribute((const void*)mma_gemm<3, 1, 1>, cudaFuncAttributeMaxDynamicSharedMemorySize, SMEM_T11);
        cudaFuncSetAttribute((const void*)mma_gemm<0, 1, 1>, cudaFuncAttributeMaxDynamicSharedMemorySize, SMEM_T11);
        if (nsm <= 0) nsm = 148;
    }

#define SYM(p, s) cudaGetSymbolAddress((void**)&p, s)
    __half *q_h, *k_h, *v_h;
    __nv_bfloat16 *A4_hi, *A4_lo, *B4_hi, *B4_lo;
    __half *C4_h, *t_h, *ZT_h, *sc_h, *at_h;
    float *part;
    SYM(q_h, g_q_h);  SYM(k_h, g_k_h);  SYM(v_h, g_v_h);
    SYM(A4_hi, g_A4_hi); SYM(A4_lo, g_A4_lo);
    SYM(B4_hi, g_B4_hi); SYM(B4_lo, g_B4_lo);
    SYM(C4_h, g_C4_h);
    SYM(t_h, g_t_h);
    SYM(ZT_h, g_ZT_h);   SYM(sc_h, g_sc_h);  SYM(at_h, g_at_h);
    SYM(part, g_part);
#undef SYM

    const long sLD = (long)L_ * D_;
    const long sLL = (long)L_ * L_;
    const long sDD = (long)D_ * D_;
    const long HDD = (long)H_ * D_ * D_;
    const float inv_sqrt_d = 1.0f / sqrtf((float)D_);

    dim3 blk(256);
    const int n4_in = (B_ * L_ * D_) / 4;

    // launch 0: q/k/v -> fp16
    dim3 gsp((n4_in + 255) / 256, 3);
    split_qkv_h<<<gsp, blk>>>((const float4*)q, (const float4*)k, (const float4*)v,
        (uint2*)q_h, (uint2*)k_h, (uint2*)v_h, n4_in);

    // launch 1: merged weight prep (bf16 2-limb A4/B4)
    dim3 gtw(D_ / 32, D_ / 32, 4 * H_);
    prep_weights<<<gtw, blk>>>(Wq, Wk, Wv, Wo, A4_hi, A4_lo, B4_hi, B4_lo);

    // launch 2: C4[z] = A4[z] @ B4[z]^T -> fp16 [MT | P]  (256 tiles, bf16x3)
    mma_gemm<3, 2, 2><<<nsm, blk, SMEM_T22>>>(A4_hi, A4_lo, B4_hi, B4_lo,
        nullptr, (__nv_bfloat16*)C4_h, nullptr,
        256, 4, 4, D_, D_, D_, D_, sDD, sDD, 1, 2 * H_, 1, 2 * H_, 1, 0, 0,
        1, sDD, 1, 0, 1.0f);

    // launch 3: ZT[b, e, h*L+m] = P[h] @ v[b]^T  (fp16 x fp16, 1024 tiles)
    mma_gemm<3, 1, 1><<<nsm, blk, SMEM_T11>>>(
        (const __nv_bfloat16*)(C4_h + HDD), nullptr,
        (const __nv_bfloat16*)v_h, nullptr,
        nullptr, (__nv_bfloat16*)ZT_h, nullptr,
        1024, 16, 4, D_, D_, D_, H_ * L_, sDD, sLD, 1, H_, H_, B_, 1, 0, 0,
        H_, (long)D_ * H_ * L_, H_, (long)L_, 1.0f);

    // launch 4: t[b,h] = q[b] @ MT[h]^T  (fp16 x fp16, 1024 tiles)
    mma_gemm<3, 1, 1><<<nsm, blk, SMEM_T11>>>(
        (const __nv_bfloat16*)q_h, nullptr,
        (const __nv_bfloat16*)C4_h, nullptr,
        nullptr, (__nv_bfloat16*)t_h, nullptr,
        1024, 4, 16, D_, D_, D_, D_, sLD, sDD, H_, B_, 1, H_, 1, 0, 0,
        1, sLD, 1, 0, 1.0f);

    // launch 5: scores = t @ k^T / sqrt(D) -> fp16 raw (fp16 x fp16, 4096 tiles)
    mma_gemm<3, 1, 1><<<nsm, blk, SMEM_T11>>>(
        (const __nv_bfloat16*)t_h, nullptr,
        (const __nv_bfloat16*)k_h, nullptr,
        nullptr, (__nv_bfloat16*)sc_h, nullptr,
        4096, 16, 16, D_, D_, D_, L_, sLD, sLD, 1, B_ * H_, H_, B_, 1, 0, 0,
        1, sLL, 1, 0, inv_sqrt_d);

    // launch 6: softmax -> fp32 attn (d_out) + fp16 copy [b,l,h,m]
    softmax_h<<<B_ * H_ * L_, blk>>>((const uint4*)sc_h, (float4*)attn, (uint4*)at_h);

    // launch 7: out partials, split-K=4 over H*L (fp16 x fp16, 512 tiles)
    mma_gemm<0, 1, 1><<<nsm, blk, SMEM_T11>>>(
        (const __nv_bfloat16*)at_h, nullptr,
        (const __nv_bfloat16*)ZT_h, nullptr,
        part, nullptr, nullptr,
        512, 4, 16, (H_ * L_) / KS_, H_ * L_, H_ * L_, D_,
        (long)L_ * H_ * L_, (long)D_ * H_ * L_, KS_, B_, KS_, B_,
        KS_, (H_ * L_) / KS_, (H_ * L_) / KS_,
        1, sLD, 1, 0, 1.0f);

    // launch 8: reduce partials -> out
    reduce_part<<<(B_ * L_ * D_ / 4) / 256, blk>>>((const float4*)part, (float4*)out);
}

// round 17
// speedup vs baseline: 1.9629x; 1.1054x over previous
#include <cuda_runtime.h>
#include <cuda_bf16.h>
#include <cuda_fp16.h>
#include <stdint.h>
#include <math.h>

#define B_  2
#define L_  2048
#define D_  512
#define H_  8
#define KS_ 4

// ======================= scratch (device globals) ==========================
__device__ __half        g_q_h [(size_t)B_*L_*D_];
__device__ __half        g_k_h [(size_t)B_*L_*D_];
__device__ __half        g_v_h [(size_t)B_*L_*D_];
__device__ __nv_bfloat16 g_A4_hi[(size_t)2*H_*D_*D_];
__device__ __nv_bfloat16 g_A4_lo[(size_t)2*H_*D_*D_];
__device__ __nv_bfloat16 g_B4_hi[(size_t)2*H_*D_*D_];
__device__ __nv_bfloat16 g_B4_lo[(size_t)2*H_*D_*D_];
__device__ __half        g_C4_h [(size_t)2*H_*D_*D_];
__device__ __half        g_t_h  [(size_t)B_*H_*L_*D_];
__device__ __half        g_ZT_h [(size_t)B_*D_*H_*L_];
__device__ __half        g_sc_h [(size_t)B_*H_*L_*L_];
__device__ __half        g_at_h [(size_t)B_*L_*H_*L_];
__device__ float         g_part [(size_t)B_*KS_*L_*D_];

// ======================= small helpers ======================================
__device__ __forceinline__ uint32_t smem_u32(const void* p) {
    uint32_t a;
    asm("{ .reg .u64 t; cvta.to.shared.u64 t, %1; cvt.u32.u64 %0, t; }"
        : "=r"(a) : "l"(p));
    return a;
}
__device__ __forceinline__ uint32_t swz128(uint32_t o) { return o ^ ((o >> 3) & 0x70); }

__device__ __forceinline__ void cp16(uint32_t s, const void* g) {
    asm volatile("cp.async.cg.shared.global [%0], [%1], 16;" :: "r"(s), "l"(g));
}
#define CP_COMMIT() asm volatile("cp.async.commit_group;" ::: "memory")

__device__ __forceinline__ void ldm4(uint32_t* r, uint32_t a) {
    asm volatile("ldmatrix.sync.aligned.m8n8.x4.shared.b16 {%0,%1,%2,%3}, [%4];"
                 : "=r"(r[0]), "=r"(r[1]), "=r"(r[2]), "=r"(r[3]) : "r"(a));
}
__device__ __forceinline__ void mma_bf16(float* c, const uint32_t* a, const uint32_t* b) {
    asm volatile("mma.sync.aligned.m16n8k16.row.col.f32.bf16.bf16.f32 "
                 "{%0,%1,%2,%3}, {%4,%5,%6,%7}, {%8,%9}, {%0,%1,%2,%3};"
                 : "+f"(c[0]), "+f"(c[1]), "+f"(c[2]), "+f"(c[3])
                 : "r"(a[0]), "r"(a[1]), "r"(a[2]), "r"(a[3]), "r"(b[0]), "r"(b[1]));
}
__device__ __forceinline__ void mma_f16(float* c, const uint32_t* a, const uint32_t* b) {
    asm volatile("mma.sync.aligned.m16n8k16.row.col.f32.f16.f16.f32 "
                 "{%0,%1,%2,%3}, {%4,%5,%6,%7}, {%8,%9}, {%0,%1,%2,%3};"
                 : "+f"(c[0]), "+f"(c[1]), "+f"(c[2]), "+f"(c[3])
                 : "r"(a[0]), "r"(a[1]), "r"(a[2]), "r"(a[3]), "r"(b[0]), "r"(b[1]));
}
__device__ __forceinline__ void split2(float x, __nv_bfloat16& h, __nv_bfloat16& l) {
    h = __float2bfloat16(x);
    l = __float2bfloat16(x - __bfloat162float(h));
}
__device__ __forceinline__ uint32_t pack_h2(float2 v) {
    __half h0 = __float2half(v.x);
    __half h1 = __float2half(v.y);
    return ((uint32_t)__half_as_ushort(h1) << 16) | __half_as_ushort(h0);
}

// ================= bf16x3 128x128 GEMM (for C4 only), fp16 out ==============
#define KC       64
#define TILE_B   (128 * 128)
#define SMEM_T22 (3 * 4 * TILE_B)   // 192 KB

struct TileP {
    const __nv_bfloat16 *ah, *al, *bh, *bl;
    long coff;
};

__global__ __launch_bounds__(256, 1)
void mma_gemm22(const __nv_bfloat16* __restrict__ Ahi, const __nv_bfloat16* __restrict__ Alo,
                const __nv_bfloat16* __restrict__ Bhi, const __nv_bfloat16* __restrict__ Blo,
                __half* __restrict__ Chi,
                int ntiles, int gx, int gy,
                int K, int lda, int ldb, int ldc,
                long sA, long sB, int amod, int bmod, long sC2, float alpha)
{
    extern __shared__ char smem[];
    const uint32_t sb = smem_u32(smem);
    const int tid  = threadIdx.x;
    const int lane = tid & 31, wid = tid >> 5;
    const int moff = (wid & 1) * 64;
    const int noff = (wid >> 1) * 32;
    constexpr int STB = 4 * TILE_B;

    int t0 = blockIdx.x;
    if (t0 >= ntiles) return;

    auto tileinfo = [&](int t) -> TileP {
        const int gxy = gx * gy;
        const int z = t / gxy;
        const int r = t - z * gxy;
        const int ty = r / gx;
        const int tx = r - ty * gx;
        const long aoff = (long)(z % amod) * sA + (long)ty * 128 * lda;
        const long boff = (long)(z % bmod) * sB + (long)tx * 128 * ldb;
        TileP p;
        p.ah = Ahi + aoff;  p.al = Alo + aoff;
        p.bh = Bhi + boff;  p.bl = Blo + boff;
        p.coff = (long)z * sC2 + (long)ty * 128 * ldc + (long)tx * 128;
        return p;
    };

#define LOADT22(T, cidx, stg) do {                                               \
        const uint32_t st = sb + (stg) * STB;                                    \
        const int k0 = (cidx) * KC;                                              \
        _Pragma("unroll")                                                        \
        for (int it = 0; it < 4; it++) {                                         \
            const int idx = tid + it * 256;                                      \
            const int row = idx >> 3, ch = idx & 7;                              \
            const uint32_t so = swz128(row * 128 + ch * 16);                     \
            const long goA = (long)row * lda + k0 + ch * 8;                      \
            const long goB = (long)row * ldb + k0 + ch * 8;                      \
            cp16(st + so,              (T).ah + goA);                            \
            cp16(st + TILE_B + so,     (T).al + goA);                            \
            cp16(st + 2 * TILE_B + so, (T).bh + goB);                            \
            cp16(st + 3 * TILE_B + so, (T).bl + goB);                            \
        }                                                                        \
    } while (0)

    const int NC = K / KC;
    const int stride = gridDim.x;

    TileP cur = tileinfo(t0);
    LOADT22(cur, 0, 0); CP_COMMIT();
    LOADT22(cur, 1, 1); CP_COMMIT();
    int lstage = 2, cstage = 0;

    const int arow = (lane & 7) + ((lane >> 3) & 1) * 8;
    const int ach  = (lane >> 4);
    const int brow = (lane & 7) + ((lane >> 4) & 1) * 8;
    const int bch  = ((lane >> 3) & 1);
    const int gq = lane >> 2, tg = lane & 3;

    for (int t = t0; t < ntiles; t += stride) {
        const int tn = t + stride;
        const bool has_next = tn < ntiles;
        TileP nxt = has_next ? tileinfo(tn) : cur;

        float acc[4][4][4];
#pragma unroll
        for (int a = 0; a < 4; a++)
#pragma unroll
            for (int b = 0; b < 4; b++)
#pragma unroll
                for (int c = 0; c < 4; c++) acc[a][b][c] = 0.f;

        for (int c = 0; c < NC; c++) {
            asm volatile("cp.async.wait_group 1;" ::: "memory");
            __syncthreads();
            const int cc = c + 2;
            if (cc < NC) {
                LOADT22(cur, cc, lstage);
            } else if (has_next && cc - NC < 2) {
                LOADT22(nxt, cc - NC, lstage);
            }
            CP_COMMIT();
            lstage = (lstage == 2) ? 0 : lstage + 1;

            const uint32_t st = sb + cstage * STB;
            cstage = (cstage == 2) ? 0 : cstage + 1;
#pragma unroll
            for (int kk = 0; kk < 4; kk++) {
                uint32_t ah[4][4], al[4][4], bh[4][2], bl[4][2];
#pragma unroll
                for (int mf = 0; mf < 4; mf++) {
                    uint32_t ad = st + swz128((moff + mf * 16 + arow) * 128 + (kk * 2 + ach) * 16);
                    ldm4(ah[mf], ad);
                    ldm4(al[mf], ad + TILE_B);
                }
#pragma unroll
                for (int p = 0; p < 2; p++) {
                    uint32_t bd = st + 2 * TILE_B +
                                  swz128((noff + p * 16 + brow) * 128 + (kk * 2 + bch) * 16);
                    uint32_t r[4];
                    ldm4(r, bd);
                    bh[2 * p][0] = r[0]; bh[2 * p][1] = r[1];
                    bh[2 * p + 1][0] = r[2]; bh[2 * p + 1][1] = r[3];
                    ldm4(r, bd + TILE_B);
                    bl[2 * p][0] = r[0]; bl[2 * p][1] = r[1];
                    bl[2 * p + 1][0] = r[2]; bl[2 * p + 1][1] = r[3];
                }
#pragma unroll
                for (int mf = 0; mf < 4; mf++)
#pragma unroll
                    for (int nf = 0; nf < 4; nf++) {
                        mma_bf16(acc[mf][nf], ah[mf], bh[nf]);
                        mma_bf16(acc[mf][nf], ah[mf], bl[nf]);
                        mma_bf16(acc[mf][nf], al[mf], bh[nf]);
                    }
            }
        }

#pragma unroll
        for (int mf = 0; mf < 4; mf++)
#pragma unroll
            for (int nf = 0; nf < 4; nf++) {
                const long row = moff + mf * 16 + gq;
                const long col = noff + nf * 8 + tg * 2;
                float v0 = alpha * acc[mf][nf][0];
                float v1 = alpha * acc[mf][nf][1];
                float v2 = alpha * acc[mf][nf][2];
                float v3 = alpha * acc[mf][nf][3];
                *reinterpret_cast<uint32_t*>(Chi + cur.coff + row * ldc + col)       = pack_h2({v0, v1});
                *reinterpret_cast<uint32_t*>(Chi + cur.coff + (row + 8) * ldc + col) = pack_h2({v2, v3});
            }
        cur = nxt;
    }
#undef LOADT22
}

// ========== wide fp16 x fp16 GEMM: CTA 128x256, warp tile 64x64 =============
// OUT: 0 fp32 C, 3 fp16 Chi
#define A_TW   (128 * 128)            // 16 KB
#define B_TW   (256 * 128)            // 32 KB
#define STB_W  (A_TW + B_TW)          // 48 KB
#define SMEM_W (3 * STB_W)            // 144 KB

struct TileW {
    const __half *a, *b;
    long coff;
};

template <int OUT>
__global__ __launch_bounds__(256, 1)
void mma_gemm_w(const __half* __restrict__ A, const __half* __restrict__ Bm,
                float* __restrict__ C, __half* __restrict__ Chi,
                int ntiles, int gx, int gy,
                int K, int lda, int ldb, int ldc,
                long sA, long sB, int adiv, int amod, int bdiv, int bmod,
                int azmod, long sA2, long sB2,
                int czdiv, long sC1, int czmod, long sC2, float alpha)
{
    extern __shared__ char smem[];
    const uint32_t sb = smem_u32(smem);
    const int tid  = threadIdx.x;
    const int lane = tid & 31, wid = tid >> 5;
    const int moff = (wid & 1) * 64;      // 2 warps over M=128
    const int noff = (wid >> 1) * 64;     // 4 warps over N=256

    int t0 = blockIdx.x;
    if (t0 >= ntiles) return;

    auto tileinfo = [&](int t) -> TileW {
        const int gxy = gx * gy;
        const int z = t / gxy;
        const int r = t - z * gxy;
        const int ty = r / gx;
        const int tx = r - ty * gx;
        TileW p;
        p.a = A + (long)((z / adiv) % amod) * sA + (long)(z % azmod) * sA2
                + (long)ty * 128 * lda;
        p.b = Bm + (long)((z / bdiv) % bmod) * sB + (long)(z % azmod) * sB2
                 + (long)tx * 256 * ldb;
        p.coff = (long)(z / czdiv) * sC1 + (long)(z % czmod) * sC2
                 + (long)ty * 128 * ldc + (long)tx * 256;
        return p;
    };

#define LOADW(T, cidx, stg) do {                                                 \
        const uint32_t st = sb + (stg) * STB_W;                                  \
        const int k0 = (cidx) * KC;                                              \
        _Pragma("unroll")                                                        \
        for (int it = 0; it < 4; it++) {                                         \
            const int idx = tid + it * 256;                                      \
            const int row = idx >> 3, ch = idx & 7;                              \
            cp16(st + swz128(row * 128 + ch * 16), (T).a + (long)row * lda + k0 + ch * 8); \
        }                                                                        \
        _Pragma("unroll")                                                        \
        for (int it = 0; it < 8; it++) {                                         \
            const int idx = tid + it * 256;                                      \
            const int row = idx >> 3, ch = idx & 7;                              \
            cp16(st + A_TW + swz128(row * 128 + ch * 16), (T).b + (long)row * ldb + k0 + ch * 8); \
        }                                                                        \
    } while (0)

    const int NC = K / KC;
    const int stride = gridDim.x;

    TileW cur = tileinfo(t0);
    LOADW(cur, 0, 0); CP_COMMIT();
    LOADW(cur, 1, 1); CP_COMMIT();
    int lstage = 2, cstage = 0;

    const int arow = (lane & 7) + ((lane >> 3) & 1) * 8;
    const int ach  = (lane >> 4);
    const int brow = (lane & 7) + ((lane >> 4) & 1) * 8;
    const int bch  = ((lane >> 3) & 1);
    const int gq = lane >> 2, tg = lane & 3;

    for (int t = t0; t < ntiles; t += stride) {
        const int tn = t + stride;
        const bool has_next = tn < ntiles;
        TileW nxt = has_next ? tileinfo(tn) : cur;

        float acc[4][8][4];
#pragma unroll
        for (int a = 0; a < 4; a++)
#pragma unroll
            for (int b = 0; b < 8; b++)
#pragma unroll
                for (int c = 0; c < 4; c++) acc[a][b][c] = 0.f;

        for (int c = 0; c < NC; c++) {
            asm volatile("cp.async.wait_group 1;" ::: "memory");
            __syncthreads();
            const int cc = c + 2;
            if (cc < NC) {
                LOADW(cur, cc, lstage);
            } else if (has_next && cc - NC < 2) {
                LOADW(nxt, cc - NC, lstage);
            }
            CP_COMMIT();
            lstage = (lstage == 2) ? 0 : lstage + 1;

            const uint32_t st = sb + cstage * STB_W;
            cstage = (cstage == 2) ? 0 : cstage + 1;
#pragma unroll
            for (int kk = 0; kk < 4; kk++) {
                uint32_t ah[4][4], bh[8][2];
#pragma unroll
                for (int mf = 0; mf < 4; mf++) {
                    uint32_t ad = st + swz128((moff + mf * 16 + arow) * 128 + (kk * 2 + ach) * 16);
                    ldm4(ah[mf], ad);
                }
#pragma unroll
                for (int p = 0; p < 4; p++) {
                    uint32_t bd = st + A_TW +
                                  swz128((noff + p * 16 + brow) * 128 + (kk * 2 + bch) * 16);
                    uint32_t r[4];
                    ldm4(r, bd);
                    bh[2 * p][0] = r[0]; bh[2 * p][1] = r[1];
                    bh[2 * p + 1][0] = r[2]; bh[2 * p + 1][1] = r[3];
                }
#pragma unroll
                for (int mf = 0; mf < 4; mf++)
#pragma unroll
                    for (int nf = 0; nf < 8; nf++)
                        mma_f16(acc[mf][nf], ah[mf], bh[nf]);
            }
        }

        // ---- epilogue ----
#pragma unroll
        for (int mf = 0; mf < 4; mf++)
#pragma unroll
            for (int nf = 0; nf < 8; nf++) {
                const long row = moff + mf * 16 + gq;
                const long col = noff + nf * 8 + tg * 2;
                float v0 = alpha * acc[mf][nf][0];
                float v1 = alpha * acc[mf][nf][1];
                float v2 = alpha * acc[mf][nf][2];
                float v3 = alpha * acc[mf][nf][3];
                if (OUT == 0) {
                    float2 p0 = {v0, v1}, p1 = {v2, v3};
                    *reinterpret_cast<float2*>(C + cur.coff + row * ldc + col)       = p0;
                    *reinterpret_cast<float2*>(C + cur.coff + (row + 8) * ldc + col) = p1;
                } else {
                    *reinterpret_cast<uint32_t*>(Chi + cur.coff + row * ldc + col)       = pack_h2({v0, v1});
                    *reinterpret_cast<uint32_t*>(Chi + cur.coff + (row + 8) * ldc + col) = pack_h2({v2, v3});
                }
            }
        cur = nxt;
    }
#undef LOADW
}

// ======================= helper kernels =====================================
__global__ __launch_bounds__(256)
void split_qkv_h(const float4* __restrict__ q, const float4* __restrict__ k,
                 const float4* __restrict__ v,
                 uint2* __restrict__ qh, uint2* __restrict__ kh,
                 uint2* __restrict__ vh, int n4)
{
    int i = blockIdx.x * 256 + threadIdx.x;
    if (i >= n4) return;
    const int sel = blockIdx.y;
    const float4* s = (sel == 0) ? q : (sel == 1) ? k : v;
    uint2* dst = (sel == 0) ? qh : (sel == 1) ? kh : vh;
    float4 x = s[i];
    uint2 o;
    o.x = pack_h2({x.x, x.y});
    o.y = pack_h2({x.z, x.w});
    dst[i] = o;
}

__global__ __launch_bounds__(256)
void prep_weights(const float* __restrict__ Wq, const float* __restrict__ Wk,
                  const float* __restrict__ Wv, const float* __restrict__ Wo,
                  __nv_bfloat16* __restrict__ A4hi, __nv_bfloat16* __restrict__ A4lo,
                  __nv_bfloat16* __restrict__ B4hi, __nv_bfloat16* __restrict__ B4lo)
{
    __shared__ float t[32][33];
    const int zz = blockIdx.z;
    const int w = zz >> 3, z = zz & 7;
    const long HDD = (long)H_ * D_ * D_;
    const int tx = threadIdx.x & 31, ty = threadIdx.x >> 5;

    if (w == 3) {
        const int e0 = blockIdx.y * 32, f0 = blockIdx.x * 32;
        const long base = HDD + (long)z * D_ * D_;
#pragma unroll
        for (int r = 0; r < 32; r += 8) {
            const int e = e0 + ty + r, f = f0 + tx;
            float x = Wo[(long)e * (H_ * D_) + (f >> 6) * 512 + z * 64 + (f & 63)];
            __nv_bfloat16 h, l;
            split2(x, h, l);
            long o = base + (long)e * D_ + f;
            A4hi[o] = h; A4lo[o] = l;
        }
        return;
    }

    const float* src = (w == 0) ? Wq : (w == 1) ? Wk : Wv;
    __nv_bfloat16* hi = (w == 0) ? B4hi : (w == 1) ? A4hi : (B4hi + HDD);
    __nv_bfloat16* lo = (w == 0) ? B4lo : (w == 1) ? A4lo : (B4lo + HDD);

    const int e0 = blockIdx.y * 32, d0 = blockIdx.x * 32;
    const float* s = src + (long)z * D_ * D_;
#pragma unroll
    for (int r = 0; r < 32; r += 8)
        t[ty + r][tx] = s[(long)(e0 + ty + r) * D_ + d0 + tx];
    __syncthreads();
    const long base = (long)z * D_ * D_;
#pragma unroll
    for (int r = 0; r < 32; r += 8) {
        float x = t[tx][ty + r];
        __nv_bfloat16 h, l;
        split2(x, h, l);
        long o = base + (long)(d0 + ty + r) * D_ + e0 + tx;
        hi[o] = h; lo[o] = l;
    }
}

__global__ __launch_bounds__(256)
void softmax_h(const uint4* __restrict__ sc, float4* __restrict__ attn,
               uint4* __restrict__ at)
{
    const int r = blockIdx.x;
    const int b = r >> 14;
    const int h = (r >> 11) & (H_ - 1);
    const int l = r & (L_ - 1);
    const int tid = threadIdx.x;

    uint4 raw = sc[(long)r * (L_ / 8) + tid];
    __half2 h2[4];
    h2[0] = *reinterpret_cast<__half2*>(&raw.x);
    h2[1] = *reinterpret_cast<__half2*>(&raw.y);
    h2[2] = *reinterpret_cast<__half2*>(&raw.z);
    h2[3] = *reinterpret_cast<__half2*>(&raw.w);
    float v[8];
#pragma unroll
    for (int i = 0; i < 4; i++) {
        float2 f = __half22float2(h2[i]);
        v[2 * i] = f.x;
        v[2 * i + 1] = f.y;
    }

    float vmax = -1e30f;
#pragma unroll
    for (int i = 0; i < 8; i++) vmax = fmaxf(vmax, v[i]);
#pragma unroll
    for (int o = 16; o > 0; o >>= 1) vmax = fmaxf(vmax, __shfl_xor_sync(0xFFFFFFFFu, vmax, o));

    __shared__ float smax[8], ssum[8];
    if ((tid & 31) == 0) smax[tid >> 5] = vmax;
    __syncthreads();
    float m = smax[0];
#pragma unroll
    for (int i = 1; i < 8; i++) m = fmaxf(m, smax[i]);

    float sum = 0.f;
#pragma unroll
    for (int i = 0; i < 8; i++) { v[i] = __expf(v[i] - m); sum += v[i]; }
#pragma unroll
    for (int o = 16; o > 0; o >>= 1) sum += __shfl_xor_sync(0xFFFFFFFFu, sum, o);
    if ((tid & 31) == 0) ssum[tid >> 5] = sum;
    __syncthreads();
    float tot = 0.f;
#pragma unroll
    for (int i = 0; i < 8; i++) tot += ssum[i];
    const float inv = 1.f / tot;

#pragma unroll
    for (int i = 0; i < 8; i++) v[i] *= inv;

    float4* arow = attn + (long)r * (L_ / 4);
    float4 f0 = {v[0], v[1], v[2], v[3]};
    float4 f1 = {v[4], v[5], v[6], v[7]};
    arow[2 * tid]     = f0;
    arow[2 * tid + 1] = f1;

    uint4 hp;
    hp.x = pack_h2({v[0], v[1]});
    hp.y = pack_h2({v[2], v[3]});
    hp.z = pack_h2({v[4], v[5]});
    hp.w = pack_h2({v[6], v[7]});
    const long ob = ((((long)b * L_ + l) * H_ + h) * L_) >> 3;
    at[ob + tid] = hp;
}

__global__ __launch_bounds__(256)
void reduce_part(const float4* __restrict__ part, float4* __restrict__ out)
{
    const int LD4 = L_ * D_ / 4;
    long idx = (long)blockIdx.x * 256 + threadIdx.x;
    int b = (int)(idx / LD4);
    long j = idx - (long)b * LD4;
    const float4* p = part + (long)b * KS_ * LD4 + j;
    float4 s = p[0];
#pragma unroll
    for (int ks = 1; ks < KS_; ks++) {
        float4 t = p[(long)ks * LD4];
        s.x += t.x; s.y += t.y; s.z += t.z; s.w += t.w;
    }
    out[idx] = s;
}

// ======================= launch =============================================
extern "C" void kernel_launch(void* const* d_in, const int* in_sizes, int n_in,
                              void* d_out, int out_size)
{
    const float* q  = (const float*)d_in[0];
    const float* k  = (const float*)d_in[1];
    const float* v  = (const float*)d_in[2];
    const float* Wq = (const float*)d_in[3];
    const float* Wk = (const float*)d_in[4];
    const float* Wv = (const float*)d_in[5];
    const float* Wo = (const float*)d_in[6];

    float* out  = (float*)d_out;
    float* attn = out + (long)B_ * L_ * D_;

    static int nsm = 0;
    if (!nsm) {
        cudaDeviceGetAttribute(&nsm, cudaDevAttrMultiProcessorCount, 0);
        cudaFuncSetAttribute((const void*)mma_gemm22, cudaFuncAttributeMaxDynamicSharedMemorySize, SMEM_T22);
        cudaFuncSetAttribute((const void*)mma_gemm_w<0>, cudaFuncAttributeMaxDynamicSharedMemorySize, SMEM_W);
        cudaFuncSetAttribute((const void*)mma_gemm_w<3>, cudaFuncAttributeMaxDynamicSharedMemorySize, SMEM_W);
        if (nsm <= 0) nsm = 148;
    }

#define SYM(p, s) cudaGetSymbolAddress((void**)&p, s)
    __half *q_h, *k_h, *v_h;
    __nv_bfloat16 *A4_hi, *A4_lo, *B4_hi, *B4_lo;
    __half *C4_h, *t_h, *ZT_h, *sc_h, *at_h;
    float *part;
    SYM(q_h, g_q_h);  SYM(k_h, g_k_h);  SYM(v_h, g_v_h);
    SYM(A4_hi, g_A4_hi); SYM(A4_lo, g_A4_lo);
    SYM(B4_hi, g_B4_hi); SYM(B4_lo, g_B4_lo);
    SYM(C4_h, g_C4_h);
    SYM(t_h, g_t_h);
    SYM(ZT_h, g_ZT_h);   SYM(sc_h, g_sc_h);  SYM(at_h, g_at_h);
    SYM(part, g_part);
#undef SYM

    const long sLD = (long)L_ * D_;
    const long sLL = (long)L_ * L_;
    const long sDD = (long)D_ * D_;
    const long HDD = (long)H_ * D_ * D_;
    const float inv_sqrt_d = 1.0f / sqrtf((float)D_);

    dim3 blk(256);
    const int n4_in = (B_ * L_ * D_) / 4;

    // launch 0: q/k/v -> fp16
    dim3 gsp((n4_in + 255) / 256, 3);
    split_qkv_h<<<gsp, blk>>>((const float4*)q, (const float4*)k, (const float4*)v,
        (uint2*)q_h, (uint2*)k_h, (uint2*)v_h, n4_in);

    // launch 1: merged weight prep
    dim3 gtw(D_ / 32, D_ / 32, 4 * H_);
    prep_weights<<<gtw, blk>>>(Wq, Wk, Wv, Wo, A4_hi, A4_lo, B4_hi, B4_lo);

    // launch 2: C4[z] = A4[z] @ B4[z]^T -> fp16  (256 tiles, bf16x3)
    mma_gemm22<<<nsm, blk, SMEM_T22>>>(A4_hi, A4_lo, B4_hi, B4_lo, C4_h,
        256, 4, 4, D_, D_, D_, D_, sDD, sDD, 2 * H_, 2 * H_, sDD, 1.0f);

    // launch 3: ZT[b, e, h*L+m] = P[h] @ v[b]^T  (wide, 512 tiles: gx=8, gy=4, z=16)
    mma_gemm_w<3><<<nsm, blk, SMEM_W>>>(C4_h + HDD, v_h,
        nullptr, ZT_h,
        512, 8, 4, D_, D_, D_, H_ * L_, sDD, sLD, 1, H_, H_, B_, 1, 0, 0,
        H_, (long)D_ * H_ * L_, H_, (long)L_, 1.0f);

    // launch 4: t[b,h] = q[b] @ MT[h]^T  (wide, 512 tiles: gx=2, gy=16, z=16)
    mma_gemm_w<3><<<nsm, blk, SMEM_W>>>(q_h, C4_h,
        nullptr, t_h,
        512, 2, 16, D_, D_, D_, D_, sLD, sDD, H_, B_, 1, H_, 1, 0, 0,
        1, sLD, 1, 0, 1.0f);

    // launch 5: scores = t @ k^T / sqrt(D) -> fp16 raw (wide, 2048 tiles: gx=8, gy=16, z=16)
    mma_gemm_w<3><<<nsm, blk, SMEM_W>>>(t_h, k_h,
        nullptr, sc_h,
        2048, 8, 16, D_, D_, D_, L_, sLD, sLD, 1, B_ * H_, H_, B_, 1, 0, 0,
        1, sLL, 1, 0, inv_sqrt_d);

    // launch 6: softmax -> fp32 attn (d_out) + fp16 copy [b,l,h,m]
    softmax_h<<<B_ * H_ * L_, blk>>>((const uint4*)sc_h, (float4*)attn, (uint4*)at_h);

    // launch 7: out partials, split-K=4 (wide, 256 tiles: gx=2, gy=16, z=8)
    mma_gemm_w<0><<<nsm, blk, SMEM_W>>>(at_h, ZT_h,
        part, nullptr,
        256, 2, 16, (H_ * L_) / KS_, H_ * L_, H_ * L_, D_,
        (long)L_ * H_ * L_, (long)D_ * H_ * L_, KS_, B_, KS_, B_,
        KS_, (H_ * L_) / KS_, (H_ * L_) / KS_,
        1, sLD, 1, 0, 1.0f);

    // launch 8: reduce partials -> out
    reduce_part<<<(B_ * L_ * D_ / 4) / 256, blk>>>((const float4*)part, (float4*)out);
}